// round 13
// baseline (speedup 1.0000x reference)
#include <cuda_runtime.h>
#include <math.h>

// Problem constants
#define NN      20000
#define EE      160000
#define INF_    64
#define EC      16
#define KD      80
#define TSTEPS  4
#define NB      10
#define NG      64
#define TPB     256
#define TMN     64            // node-GEMM rows per tile
#define NIS     68            // node smem dword row stride
#define NTILEN  ((NN + TMN - 1) / TMN + NB)

#define NODE_SMEM ((64*NIS + TMN*NIS) * 4 + TMN * 4)
#define MLP_SMEM  ((NG*10 + NG*128 + NG*64) * 4)

// ---------------- device scratch (zero at load; kept zeroed by k_mlp each call) ----------------
__device__ int   g_deg[NN];      // out-degree (bucket)
__device__ int   g_indeg[NN];    // in-degree (CSR)
__device__ int   g_dptr[NN + 1];
__device__ int   g_dcur[NN];
__device__ int   g_srcCSR[EE];   // src | bucket<<20, in dst-CSR order
__device__ int   g_eCSR[EE];     // edge id, in dst-CSR order
__device__ int   g_ncursor[NB];
__device__ int   g_nperm[NB * NN];
__device__ float g_y[NN * INF_];
__device__ float g_xA[NN * INF_];
__device__ float g_xB[NN * INF_];
__device__ float g_pooled[NG * 10];

// ---------------- helpers ----------------
__device__ __forceinline__ unsigned f2tf32(float f) {
    unsigned u; asm("cvt.rna.tf32.f32 %0, %1;" : "=r"(u) : "f"(f)); return u;
}
__device__ __forceinline__ void mma_tf32(float* c, unsigned a0, unsigned a1, unsigned a2, unsigned a3,
                                         unsigned b0, unsigned b1) {
    asm volatile("mma.sync.aligned.m16n8k8.row.col.f32.tf32.tf32.f32 "
                 "{%0,%1,%2,%3}, {%4,%5,%6,%7}, {%8,%9}, {%0,%1,%2,%3};"
                 : "+f"(c[0]), "+f"(c[1]), "+f"(c[2]), "+f"(c[3])
                 : "r"(a0), "r"(a1), "r"(a2), "r"(a3), "r"(b0), "r"(b1));
}
// sigmoid(x) = 0.5*tanh(x/2) + 0.5  (single MUFU via tanh.approx)
__device__ __forceinline__ float sigf(float x) {
    float t;
    float h = 0.5f * x;
    asm("tanh.approx.f32 %0, %1;" : "=f"(t) : "f"(h));
    return fmaf(0.5f, t, 0.5f);
}

// ---------------- preprocessing ----------------
__global__ void k_deg(const int* __restrict__ ei) {
    int e = blockIdx.x * blockDim.x + threadIdx.x;
    if (e < EE) {
        atomicAdd(&g_deg[ei[e]], 1);
        atomicAdd(&g_indeg[ei[EE + e]], 1);
    }
}

#define SCH 20
__global__ __launch_bounds__(1024) void k_dscan() {
    __shared__ int ssum[1024];
    int t = threadIdx.x;
    int lo = t * SCH, hi = min(lo + SCH, NN);
    int s = 0;
    for (int i = lo; i < hi; i++) s += g_indeg[i];
    ssum[t] = s;
    __syncthreads();
    for (int off = 1; off < 1024; off <<= 1) {
        int v = 0;
        if (t >= off) v = ssum[t - off];
        __syncthreads();
        if (t >= off) ssum[t] += v;
        __syncthreads();
    }
    int pre = (t == 0) ? 0 : ssum[t - 1];
    for (int i = lo; i < hi; i++) { g_dptr[i] = pre; pre += g_indeg[i]; }
    if (lo < NN && hi == NN) g_dptr[NN] = pre;
}

// fused: edge CSR scatter (spread-address atomics) + node bucket scatter (two-level)
__global__ void k_scatterAll(const int* __restrict__ ei) {
    __shared__ int ncnt[NB], nrn[NB];
    int tid = threadIdx.x;
    if (tid < NB) ncnt[tid] = 0;
    __syncthreads();
    int idx = blockIdx.x * blockDim.x + tid;
    int nb = -1, npos = 0;
    if (idx < NN) {
        nb = min(g_deg[idx] + 1, NB) - 1;
        npos = atomicAdd(&ncnt[nb], 1);
    }
    __syncthreads();
    if (tid < NB) nrn[tid] = ncnt[tid] ? atomicAdd(&g_ncursor[tid], ncnt[tid]) : 0;
    __syncthreads();
    if (idx < NN) g_nperm[nb * NN + nrn[nb] + npos] = idx;

    if (idx < EE) {
        int src = ei[idx];
        int b = min(g_deg[src] + 1, NB) - 1;
        int d = ei[EE + idx];
        int pos = atomicAdd(&g_dcur[d], 1);
        int slot = g_dptr[d] + pos;
        g_srcCSR[slot] = src | (b << 20);
        g_eCSR[slot] = idx;
    }
}

// ---------------- node GEMM: y = x @ W_top[bucket(n)] ----------------
__global__ __launch_bounds__(TPB, 4) void k_node(
    const float* __restrict__ xin, const float* __restrict__ Wt)
{
    extern __shared__ unsigned sm[];
    unsigned* Wts = sm;                   // [64][32 pairs] stride NIS
    unsigned* A   = sm + 64 * NIS;        // [TMN][32 pairs] stride NIS
    int* nidS = (int*)(A + TMN * NIS);

    const int tid = threadIdx.x;
    __shared__ int scnt[NB];
    __shared__ int s_bucket, s_loc, s_cnt;
    if (tid < NB) scnt[tid] = g_ncursor[tid];
    __syncthreads();
    if (tid == 0) {
        int acc = 0, b = -1, loc = 0, cnt = 0;
        #pragma unroll
        for (int i = 0; i < NB; i++) {
            int nt = (scnt[i] + TMN - 1) >> 6;
            if (b < 0 && (int)blockIdx.x < acc + nt) { b = i; loc = blockIdx.x - acc; cnt = scnt[i]; }
            acc += nt;
        }
        s_bucket = b; s_loc = loc; s_cnt = cnt;
    }
    __syncthreads();
    const int bucket = s_bucket;
    if (bucket < 0) return;
    const int cnt  = s_cnt;
    const int base = s_loc * TMN;

    const float* Wg = Wt + bucket * KD * 64;
    #pragma unroll
    for (int idx = tid; idx < 64 * 32; idx += TPB) {
        int c = idx & 63, p = idx >> 6;
        int kc = p >> 2, j = p & 3;
        int r0 = kc * 8 + j;
        uint2 u = make_uint2(f2tf32(Wg[r0 * 64 + c]), f2tf32(Wg[(r0 + 4) * 64 + c]));
        *(uint2*)(Wts + c * NIS + p * 2) = u;
    }
    if (tid < TMN)
        nidS[tid] = (base + tid < cnt) ? g_nperm[bucket * NN + base + tid] : -1;
    __syncthreads();

    const float4* xin4 = (const float4*)xin;
    #pragma unroll
    for (int idx = tid; idx < TMN * 8; idx += TPB) {
        int r = idx >> 3, kc = idx & 7;
        int nid = nidS[r];
        float4 v0 = make_float4(0.f,0.f,0.f,0.f), v1 = v0;
        if (nid >= 0) { v0 = xin4[nid * 16 + kc * 2]; v1 = xin4[nid * 16 + kc * 2 + 1]; }
        unsigned* p = A + r * NIS + kc * 8;
        *(uint2*)(p + 0) = make_uint2(f2tf32(v0.x), f2tf32(v1.x));
        *(uint2*)(p + 2) = make_uint2(f2tf32(v0.y), f2tf32(v1.y));
        *(uint2*)(p + 4) = make_uint2(f2tf32(v0.z), f2tf32(v1.z));
        *(uint2*)(p + 6) = make_uint2(f2tf32(v0.w), f2tf32(v1.w));
    }
    __syncthreads();

    const int warp = tid >> 5, lane = tid & 31;
    const int g = lane >> 2, tg = lane & 3;
    const int rowbase = (warp >> 1) * 16;
    const int ch = warp & 1;

    float acc[4][4];
    #pragma unroll
    for (int n = 0; n < 4; n++)
        #pragma unroll
        for (int j = 0; j < 4; j++) acc[n][j] = 0.f;

    const unsigned* A0 = A + (rowbase + g) * NIS + tg * 2;
    const unsigned* A1 = A0 + 8 * NIS;
    const unsigned* Bb = Wts + (ch * 32 + g) * NIS + tg * 2;

    #pragma unroll
    for (int kc = 0; kc < 8; kc++) {
        const int ko = kc * 8;
        uint2 pa0 = *(const uint2*)(A0 + ko);
        uint2 pa1 = *(const uint2*)(A1 + ko);
        #pragma unroll
        for (int nc = 0; nc < 4; nc++) {
            uint2 pb = *(const uint2*)(Bb + nc * 8 * NIS + ko);
            mma_tf32(acc[nc], pa0.x, pa1.x, pa0.y, pa1.y, pb.x, pb.y);
        }
    }

    const int r0 = rowbase + g, r1 = r0 + 8;
    const int n0 = nidS[r0], n1 = nidS[r1];
    #pragma unroll
    for (int nc = 0; nc < 4; nc++) {
        int coff = ch * 32 + nc * 8 + tg * 2;
        if (n0 >= 0) *(float2*)(g_y + n0 * 64 + coff) = make_float2(acc[nc][0], acc[nc][1]);
        if (n1 >= 0) *(float2*)(g_y + n1 * 64 + coff) = make_float2(acc[nc][2], acc[nc][3]);
    }
}

// ---------------- fused edge transform + aggregation (dst-stationary) ----------------
// x'[n] = sigf(y[n]) + sum_{edges->n} sigf(ea[e] @ W_bot[b(src)] + y[src])
// one warp per node; lane owns 2 columns; all global accesses warp-coalesced; no atomics.
__global__ __launch_bounds__(TPB, 4) void k_fused(
    const float* __restrict__ ea, const float* __restrict__ Wt,
    float* __restrict__ xout)
{
    __shared__ float Wsm[NB * EC * 64];   // 40KB: all 10 W_bot matrices
    int tid = threadIdx.x;
    const float4* Wt4 = (const float4*)Wt;
    #pragma unroll
    for (int i = tid; i < NB * EC * 16; i += TPB) {      // float4 units
        int b = i >> 8, r = i & 255;                      // 256 f4 per bucket
        ((float4*)Wsm)[i] = Wt4[b * (KD * 16) + 64 * 16 + r];
    }
    __syncthreads();

    int warp = tid >> 5, lane = tid & 31;
    int n = blockIdx.x * 8 + warp;
    if (n >= NN) return;

    float2 yv = *(const float2*)(g_y + n * 64 + lane * 2);
    float2 acc = make_float2(sigf(yv.x), sigf(yv.y));

    int beg = g_dptr[n], end = g_dptr[n + 1];
    if (beg < end) {
        int se = g_srcCSR[beg];
        int e  = g_eCSR[beg];
        float eav = ea[e * EC + (lane & 15)];
        for (int i = beg; i < end; i++) {
            // prefetch next edge
            int se2 = 0, e2 = 0; float eav2 = 0.f;
            if (i + 1 < end) {
                se2 = g_srcCSR[i + 1];
                e2  = g_eCSR[i + 1];
                eav2 = ea[e2 * EC + (lane & 15)];
            }
            int src = se & 0xFFFFF, b = se >> 20;
            float2 ys = *(const float2*)(g_y + src * 64 + lane * 2);
            const float* Wb = Wsm + b * (EC * 64) + lane * 2;
            float zx = 0.f, zy = 0.f;
            #pragma unroll
            for (int k = 0; k < EC; k++) {
                float ek = __shfl_sync(0xffffffffu, eav, k, 16);
                float2 w = *(const float2*)(Wb + k * 64);
                zx = fmaf(ek, w.x, zx);
                zy = fmaf(ek, w.y, zy);
            }
            acc.x += sigf(zx + ys.x);
            acc.y += sigf(zy + ys.y);
            se = se2; e = e2; eav = eav2;
        }
    }
    *(float2*)(xout + n * 64 + lane * 2) = acc;
}

// ---------------- readout ----------------
__global__ __launch_bounds__(TPB) void k_readout(
    const float* __restrict__ x, const float* __restrict__ Wread,
    const int* __restrict__ batch)
{
    __shared__ float Ws[TSTEPS * INF_ * 10];
    for (int i = threadIdx.x; i < TSTEPS * INF_ * 10; i += TPB) Ws[i] = Wread[i];
    __syncthreads();

    int n = blockIdx.x * blockDim.x + threadIdx.x;
    if (n >= NN) return;

    float xr[INF_];
    const float4* xp = (const float4*)(x + n * INF_);
    #pragma unroll
    for (int q = 0; q < INF_ / 4; q++) {
        float4 f = xp[q];
        xr[q*4+0] = f.x; xr[q*4+1] = f.y; xr[q*4+2] = f.z; xr[q*4+3] = f.w;
    }

    float accq[10];
    #pragma unroll
    for (int j = 0; j < 10; j++) accq[j] = 0.f;

    for (int t = 0; t < TSTEPS; t++) {
        float l[10];
        #pragma unroll
        for (int j = 0; j < 10; j++) l[j] = 0.f;
        const float* W = Ws + t * INF_ * 10;
        #pragma unroll 4
        for (int k = 0; k < INF_; k++) {
            float xv = xr[k];
            #pragma unroll
            for (int j = 0; j < 10; j++) l[j] += xv * W[k * 10 + j];
        }
        float m = l[0];
        #pragma unroll
        for (int j = 1; j < 10; j++) m = fmaxf(m, l[j]);
        float ssum = 0.f;
        #pragma unroll
        for (int j = 0; j < 10; j++) { l[j] = __expf(l[j] - m); ssum += l[j]; }
        float inv = 1.f / ssum;
        #pragma unroll
        for (int j = 0; j < 10; j++) accq[j] += l[j] * inv;
    }

    int g = batch[n];
    #pragma unroll
    for (int j = 0; j < 10; j++) atomicAdd(&g_pooled[g * 10 + j], accq[j]);
}

// ---------------- final MLP + graph-state reset ----------------
__global__ __launch_bounds__(TPB) void k_mlp(
    const float* __restrict__ fc1w, const float* __restrict__ fc1b,
    const float* __restrict__ fc2w, const float* __restrict__ fc2b,
    const float* __restrict__ fc3w, const float* __restrict__ fc3b,
    float* __restrict__ out)
{
    extern __shared__ float smf[];
    float* P  = smf;
    float* H1 = P + NG * 10;
    float* H2 = H1 + NG * 128;
    int tid = threadIdx.x;

    for (int i = tid; i < NG * 10; i += TPB) P[i] = g_pooled[i];
    __syncthreads();

    // reset device state so the graph is replay-invariant
    for (int i = tid; i < NN; i += TPB) { g_deg[i] = 0; g_indeg[i] = 0; g_dcur[i] = 0; }
    if (tid < NB) g_ncursor[tid] = 0;
    for (int i = tid; i < NG * 10; i += TPB) g_pooled[i] = 0.f;

    for (int idx = tid; idx < NG * 128; idx += TPB) {
        int g = idx >> 7, j = idx & 127;
        float a = fc1b[j];
        #pragma unroll
        for (int k = 0; k < 10; k++) a += P[g * 10 + k] * fc1w[k * 128 + j];
        H1[idx] = a > 0.f ? a : 0.01f * a;
    }
    __syncthreads();

    for (int idx = tid; idx < NG * 64; idx += TPB) {
        int g = idx >> 6, j = idx & 63;
        float a = fc2b[j];
        #pragma unroll 8
        for (int k = 0; k < 128; k++) a += H1[g * 128 + k] * fc2w[k * 64 + j];
        H2[idx] = a > 0.f ? a : 0.01f * a;
    }
    __syncthreads();

    for (int g = tid; g < NG; g += TPB) {
        float a = fc3b[0];
        #pragma unroll 8
        for (int k = 0; k < 64; k++) a += H2[g * 64 + k] * fc3w[k];
        out[g] = a > 0.f ? a : 0.01f * a;
    }
}

// ---------------- launch ----------------
extern "C" void kernel_launch(void* const* d_in, const int* in_sizes, int n_in,
                              void* d_out, int out_size)
{
    const float* x     = (const float*)d_in[0];
    const float* ea    = (const float*)d_in[1];
    const float* Wmsg  = (const float*)d_in[2];
    const float* Wread = (const float*)d_in[3];
    const float* fc1w  = (const float*)d_in[4];
    const float* fc1b  = (const float*)d_in[5];
    const float* fc2w  = (const float*)d_in[6];
    const float* fc2b  = (const float*)d_in[7];
    const float* fc3w  = (const float*)d_in[8];
    const float* fc3b  = (const float*)d_in[9];
    const int*   ei    = (const int*)d_in[10];
    const int*   batch = (const int*)d_in[11];
    float* out = (float*)d_out;

    cudaFuncSetAttribute(k_node, cudaFuncAttributeMaxDynamicSharedMemorySize, NODE_SMEM);
    cudaFuncSetAttribute(k_mlp,  cudaFuncAttributeMaxDynamicSharedMemorySize, MLP_SMEM);

    void *pA = nullptr, *pB = nullptr;
    cudaGetSymbolAddress(&pA, g_xA);
    cudaGetSymbolAddress(&pB, g_xB);

    k_deg<<<(EE + TPB - 1) / TPB, TPB>>>(ei);                       // 0
    k_dscan<<<1, 1024>>>();                                         // 1
    k_scatterAll<<<(EE + TPB - 1) / TPB, TPB>>>(ei);                // 2

    const float* xin = x;
    for (int t = 0; t < TSTEPS; t++) {
        const float* Wt = Wmsg + (size_t)t * NB * KD * INF_;
        float* xo = (t % 2 == 0) ? (float*)pB : (float*)pA;
        k_node<<<NTILEN, TPB, NODE_SMEM>>>(xin, Wt);                // 3 (t=0)
        k_fused<<<(NN + 7) / 8, TPB>>>(ea, Wt, xo);                 // 4 (t=0)
        xin = xo;
    }

    k_readout<<<(NN + TPB - 1) / TPB, TPB>>>(xin, Wread, batch);
    k_mlp<<<1, TPB, MLP_SMEM>>>(fc1w, fc1b, fc2w, fc2b, fc3w, fc3b, out);
}

// round 14
// speedup vs baseline: 1.2632x; 1.2632x over previous
#include <cuda_runtime.h>
#include <math.h>

// Problem constants
#define NN      20000
#define EE      160000
#define INF_    64
#define EC      16
#define KD      80
#define TSTEPS  4
#define NB      10
#define NG      64
#define TPB     256
#define TMN     64            // node-GEMM rows per tile
#define TME     128           // edge-GEMM rows per tile
#define NIS     68            // node smem dword row stride
#define EIS     20            // edge smem dword row stride
#define NTILEN  ((NN + TMN - 1) / TMN + NB)
#define NTILEE  ((EE + TME - 1) / TME + NB)

#define NODE_SMEM ((64*NIS + TMN*NIS) * 4 + TMN * 4)
#define EDGE_SMEM ((64*EIS + TME*EIS) * 4 + 3 * TME * 4)
#define MLP_SMEM  ((NG*10 + NG*128 + NG*64) * 4)

// ---------------- device scratch (zero at load; kept zeroed by k_mlp each call) ----------------
__device__ int   g_deg[NN];        // out-degree
__device__ int   g_nbcnt[NB];      // node count per bucket
__device__ int   g_ebcnt[NB];      // edge count per bucket
__device__ int   g_ncur[NB];       // node scatter cursors
__device__ int   g_ecur[NN];       // per-src edge cursors (spread atomics)
__device__ int   g_nbStart[NB + 1];
__device__ int   g_ebStart[NB + 1];
__device__ int   g_rank[NN];       // node -> bucket-major rank
__device__ int   g_npermG[NN];     // rank -> node
__device__ int   g_eptr[NN + 1];   // rank -> first edge slot (src-CSR)
__device__ int   g_perm[EE];       // edge ids, bucket-major src-minor order
__device__ float g_y[NN * INF_];
__device__ float g_xA[NN * INF_];
__device__ float g_xB[NN * INF_];
__device__ float g_pooled[NG * 10];

// ---------------- helpers ----------------
__device__ __forceinline__ unsigned f2tf32(float f) {
    unsigned u; asm("cvt.rna.tf32.f32 %0, %1;" : "=r"(u) : "f"(f)); return u;
}
__device__ __forceinline__ void mma_tf32(float* c, unsigned a0, unsigned a1, unsigned a2, unsigned a3,
                                         unsigned b0, unsigned b1) {
    asm volatile("mma.sync.aligned.m16n8k8.row.col.f32.tf32.tf32.f32 "
                 "{%0,%1,%2,%3}, {%4,%5,%6,%7}, {%8,%9}, {%0,%1,%2,%3};"
                 : "+f"(c[0]), "+f"(c[1]), "+f"(c[2]), "+f"(c[3])
                 : "r"(a0), "r"(a1), "r"(a2), "r"(a3), "r"(b0), "r"(b1));
}
// sigmoid(x) = 0.5*tanh(x/2) + 0.5  (single MUFU via tanh.approx)
__device__ __forceinline__ float sigf(float x) {
    float t;
    float h = 0.5f * x;
    asm("tanh.approx.f32 %0, %1;" : "=f"(t) : "f"(h));
    return fmaf(0.5f, t, 0.5f);
}
__device__ __forceinline__ void red4(float* p, float4 v) {
    asm volatile("red.global.add.v4.f32 [%0], {%1, %2, %3, %4};"
                 :: "l"(p), "f"(v.x), "f"(v.y), "f"(v.z), "f"(v.w) : "memory");
}

// ---------------- preprocessing ----------------
__global__ void k_deg(const int* __restrict__ ei) {
    int e = blockIdx.x * blockDim.x + threadIdx.x;
    if (e < EE) atomicAdd(&g_deg[ei[e]], 1);
}

// two-level bucket histograms: node counts + edge counts per bucket
__global__ void k_hist() {
    __shared__ int nb[NB], eb[NB];
    int tid = threadIdx.x;
    if (tid < NB) { nb[tid] = 0; eb[tid] = 0; }
    __syncthreads();
    int n = blockIdx.x * blockDim.x + tid;
    if (n < NN) {
        int d = g_deg[n];
        int b = min(d + 1, NB) - 1;
        atomicAdd(&nb[b], 1);
        atomicAdd(&eb[b], d);
    }
    __syncthreads();
    if (tid < NB) {
        if (nb[tid]) atomicAdd(&g_nbcnt[tid], nb[tid]);
        if (eb[tid]) atomicAdd(&g_ebcnt[tid], eb[tid]);
    }
}

__global__ void k_start() {
    if (threadIdx.x == 0 && blockIdx.x == 0) {
        int a = 0, c = 0;
        #pragma unroll
        for (int b = 0; b < NB; b++) {
            g_nbStart[b] = a; a += g_nbcnt[b];
            g_ebStart[b] = c; c += g_ebcnt[b];
        }
        g_nbStart[NB] = a;
        g_ebStart[NB] = c;
    }
}

// node scatter: assign bucket-major rank; two-level
__global__ void k_nscatter() {
    __shared__ int cnt[NB], rng[NB];
    int tid = threadIdx.x;
    if (tid < NB) cnt[tid] = 0;
    __syncthreads();
    int n = blockIdx.x * blockDim.x + tid;
    int b = -1, pos = 0;
    if (n < NN) {
        b = min(g_deg[n] + 1, NB) - 1;
        pos = atomicAdd(&cnt[b], 1);
    }
    __syncthreads();
    if (tid < NB) rng[tid] = cnt[tid] ? atomicAdd(&g_ncur[tid], cnt[tid]) : 0;
    __syncthreads();
    if (n < NN) {
        int rank = g_nbStart[b] + rng[b] + pos;
        g_rank[n] = rank;
        g_npermG[rank] = n;
    }
}

// exclusive scan of out-degrees in rank order -> g_eptr
#define SCH 20
__global__ __launch_bounds__(1024) void k_eptr() {
    __shared__ int ssum[1024];
    int t = threadIdx.x;
    int lo = t * SCH, hi = min(lo + SCH, NN);
    int s = 0;
    for (int i = lo; i < hi; i++) s += g_deg[g_npermG[i]];
    ssum[t] = s;
    __syncthreads();
    for (int off = 1; off < 1024; off <<= 1) {
        int v = 0;
        if (t >= off) v = ssum[t - off];
        __syncthreads();
        if (t >= off) ssum[t] += v;
        __syncthreads();
    }
    int pre = (t == 0) ? 0 : ssum[t - 1];
    for (int i = lo; i < hi; i++) { g_eptr[i] = pre; pre += g_deg[g_npermG[i]]; }
    if (lo < NN && hi == NN) g_eptr[NN] = pre;
}

// edge scatter into src-CSR (bucket-major, src-minor) slots; spread atomics
__global__ void k_escatter(const int* __restrict__ ei) {
    int e = blockIdx.x * blockDim.x + threadIdx.x;
    if (e < EE) {
        int src = ei[e];
        int slot = g_eptr[g_rank[src]] + atomicAdd(&g_ecur[src], 1);
        g_perm[slot] = e;
    }
}

// ---------------- node GEMM: y = x @ W_top[bucket(n)]; xout init = sigf(y) ----------------
__global__ __launch_bounds__(TPB, 4) void k_node(
    const float* __restrict__ xin, const float* __restrict__ Wt,
    float* __restrict__ xout)
{
    extern __shared__ unsigned sm[];
    unsigned* Wts = sm;                   // [64][32 pairs] stride NIS
    unsigned* A   = sm + 64 * NIS;        // [TMN][32 pairs] stride NIS
    int* nidS = (int*)(A + TMN * NIS);

    const int tid = threadIdx.x;
    __shared__ int sst[NB + 1];
    __shared__ int s_bucket, s_loc, s_cnt;
    if (tid < NB + 1) sst[tid] = g_nbStart[tid];
    __syncthreads();
    if (tid == 0) {
        int acc = 0, b = -1, loc = 0, cnt = 0;
        #pragma unroll
        for (int i = 0; i < NB; i++) {
            int c = sst[i + 1] - sst[i];
            int nt = (c + TMN - 1) >> 6;
            if (b < 0 && (int)blockIdx.x < acc + nt) { b = i; loc = blockIdx.x - acc; cnt = c; }
            acc += nt;
        }
        s_bucket = b; s_loc = loc; s_cnt = cnt;
    }
    __syncthreads();
    const int bucket = s_bucket;
    if (bucket < 0) return;
    const int cnt  = s_cnt;
    const int base = s_loc * TMN;
    const int nbase = sst[bucket];

    const float* Wg = Wt + bucket * KD * 64;
    #pragma unroll
    for (int idx = tid; idx < 64 * 32; idx += TPB) {
        int c = idx & 63, p = idx >> 6;
        int kc = p >> 2, j = p & 3;
        int r0 = kc * 8 + j;
        uint2 u = make_uint2(f2tf32(Wg[r0 * 64 + c]), f2tf32(Wg[(r0 + 4) * 64 + c]));
        *(uint2*)(Wts + c * NIS + p * 2) = u;
    }
    if (tid < TMN)
        nidS[tid] = (base + tid < cnt) ? g_npermG[nbase + base + tid] : -1;
    __syncthreads();

    const float4* xin4 = (const float4*)xin;
    #pragma unroll
    for (int idx = tid; idx < TMN * 8; idx += TPB) {
        int r = idx >> 3, kc = idx & 7;
        int nid = nidS[r];
        float4 v0 = make_float4(0.f,0.f,0.f,0.f), v1 = v0;
        if (nid >= 0) { v0 = xin4[nid * 16 + kc * 2]; v1 = xin4[nid * 16 + kc * 2 + 1]; }
        unsigned* p = A + r * NIS + kc * 8;
        *(uint2*)(p + 0) = make_uint2(f2tf32(v0.x), f2tf32(v1.x));
        *(uint2*)(p + 2) = make_uint2(f2tf32(v0.y), f2tf32(v1.y));
        *(uint2*)(p + 4) = make_uint2(f2tf32(v0.z), f2tf32(v1.z));
        *(uint2*)(p + 6) = make_uint2(f2tf32(v0.w), f2tf32(v1.w));
    }
    __syncthreads();

    const int warp = tid >> 5, lane = tid & 31;
    const int g = lane >> 2, tg = lane & 3;
    const int rowbase = (warp >> 1) * 16;
    const int ch = warp & 1;

    float acc[4][4];
    #pragma unroll
    for (int n = 0; n < 4; n++)
        #pragma unroll
        for (int j = 0; j < 4; j++) acc[n][j] = 0.f;

    const unsigned* A0 = A + (rowbase + g) * NIS + tg * 2;
    const unsigned* A1 = A0 + 8 * NIS;
    const unsigned* Bb = Wts + (ch * 32 + g) * NIS + tg * 2;

    #pragma unroll
    for (int kc = 0; kc < 8; kc++) {
        const int ko = kc * 8;
        uint2 pa0 = *(const uint2*)(A0 + ko);
        uint2 pa1 = *(const uint2*)(A1 + ko);
        #pragma unroll
        for (int nc = 0; nc < 4; nc++) {
            uint2 pb = *(const uint2*)(Bb + nc * 8 * NIS + ko);
            mma_tf32(acc[nc], pa0.x, pa1.x, pa0.y, pa1.y, pb.x, pb.y);
        }
    }

    const int r0 = rowbase + g, r1 = r0 + 8;
    const int n0 = nidS[r0], n1 = nidS[r1];
    #pragma unroll
    for (int nc = 0; nc < 4; nc++) {
        int coff = ch * 32 + nc * 8 + tg * 2;
        if (n0 >= 0) {
            *(float2*)(g_y + n0 * 64 + coff) = make_float2(acc[nc][0], acc[nc][1]);
            *(float2*)(xout + n0 * 64 + coff) = make_float2(sigf(acc[nc][0]), sigf(acc[nc][1]));
        }
        if (n1 >= 0) {
            *(float2*)(g_y + n1 * 64 + coff) = make_float2(acc[nc][2], acc[nc][3]);
            *(float2*)(xout + n1 * 64 + coff) = make_float2(sigf(acc[nc][2]), sigf(acc[nc][3]));
        }
    }
}

// ---------------- edge GEMM + fused aggregation (v4 epilogue, src-sorted tiles) ----------------
__global__ __launch_bounds__(TPB, 4) void k_edge(
    const float* __restrict__ ea, const int* __restrict__ ei,
    const float* __restrict__ Wt, float* __restrict__ xout)
{
    extern __shared__ unsigned sm[];
    unsigned* Wts = sm;                   // [64][8 pairs] stride EIS
    unsigned* A   = sm + 64 * EIS;        // [TME][8 pairs] stride EIS
    int* eS   = (int*)(A + TME * EIS);
    int* srcS = eS + TME;
    int* dstS = srcS + TME;

    const int tid = threadIdx.x;
    __shared__ int sst[NB + 1];
    __shared__ int s_bucket, s_loc, s_cnt;
    if (tid < NB + 1) sst[tid] = g_ebStart[tid];
    __syncthreads();
    if (tid == 0) {
        int acc = 0, b = -1, loc = 0, cnt = 0;
        #pragma unroll
        for (int i = 0; i < NB; i++) {
            int c = sst[i + 1] - sst[i];
            int nt = (c + TME - 1) >> 7;
            if (b < 0 && (int)blockIdx.x < acc + nt) { b = i; loc = blockIdx.x - acc; cnt = c; }
            acc += nt;
        }
        s_bucket = b; s_loc = loc; s_cnt = cnt;
    }
    __syncthreads();
    const int bucket = s_bucket;
    if (bucket < 0) return;
    const int cnt  = s_cnt;
    const int base = s_loc * TME;
    const int ebase = sst[bucket];

    const float* Wg = Wt + bucket * KD * 64;
    #pragma unroll
    for (int idx = tid; idx < 64 * 8; idx += TPB) {
        int c = idx & 63, p = idx >> 6;
        int kc = p >> 2, j = p & 3;
        int r0 = 64 + kc * 8 + j;
        uint2 u = make_uint2(f2tf32(Wg[r0 * 64 + c]), f2tf32(Wg[(r0 + 4) * 64 + c]));
        *(uint2*)(Wts + c * EIS + p * 2) = u;
    }
    for (int r = tid; r < TME; r += TPB) {
        int e = -1, s = 0, d = -1;
        if (base + r < cnt) {
            e = g_perm[ebase + base + r];
            s = ei[e];
            d = ei[EE + e];
        }
        eS[r] = e; srcS[r] = s; dstS[r] = d;
    }
    __syncthreads();

    const float4* ea4 = (const float4*)ea;
    for (int idx = tid; idx < TME * 2; idx += TPB) {
        int r = idx >> 1, kc = idx & 1;
        int e = eS[r];
        float4 v0 = make_float4(0.f,0.f,0.f,0.f), v1 = v0;
        if (e >= 0) { v0 = ea4[e * 4 + kc * 2]; v1 = ea4[e * 4 + kc * 2 + 1]; }
        unsigned* p = A + r * EIS + kc * 8;
        *(uint2*)(p + 0) = make_uint2(f2tf32(v0.x), f2tf32(v1.x));
        *(uint2*)(p + 2) = make_uint2(f2tf32(v0.y), f2tf32(v1.y));
        *(uint2*)(p + 4) = make_uint2(f2tf32(v0.z), f2tf32(v1.z));
        *(uint2*)(p + 6) = make_uint2(f2tf32(v0.w), f2tf32(v1.w));
    }
    __syncthreads();

    const int warp = tid >> 5, lane = tid & 31;
    const int g = lane >> 2, tg = lane & 3;
    const int rowbase = warp * 16;

    float acc[8][4];
    #pragma unroll
    for (int n = 0; n < 8; n++)
        #pragma unroll
        for (int j = 0; j < 4; j++) acc[n][j] = 0.f;

    const unsigned* A0 = A + (rowbase + g) * EIS + tg * 2;
    const unsigned* A1 = A0 + 8 * EIS;
    const unsigned* Bb = Wts + g * EIS + tg * 2;

    #pragma unroll
    for (int kc = 0; kc < 2; kc++) {
        const int ko = kc * 8;
        uint2 pa0 = *(const uint2*)(A0 + ko);
        uint2 pa1 = *(const uint2*)(A1 + ko);
        #pragma unroll
        for (int nc = 0; nc < 8; nc++) {
            uint2 pb = *(const uint2*)(Bb + nc * 8 * EIS + ko);
            mma_tf32(acc[nc], pa0.x, pa1.x, pa0.y, pa1.y, pb.x, pb.y);
        }
    }

    // epilogue: lane-pair shuffle -> v4 gather (src-coalesced) + v4 reduction
    const int r0 = rowbase + g, r1 = r0 + 8;
    const bool odd = tg & 1;
    const int myE = odd ? eS[r1]   : eS[r0];
    const int myS = odd ? srcS[r1] : srcS[r0];
    const int myD = odd ? dstS[r1] : dstS[r0];
    const int colbase = (tg & ~1) * 2;
    #pragma unroll
    for (int nc = 0; nc < 8; nc++) {
        float sx = odd ? acc[nc][0] : acc[nc][2];
        float sy = odd ? acc[nc][1] : acc[nc][3];
        float rx = __shfl_xor_sync(0xffffffffu, sx, 1);
        float ry = __shfl_xor_sync(0xffffffffu, sy, 1);
        float4 z4;
        if (odd) { z4.x = rx;          z4.y = ry;          z4.z = acc[nc][2]; z4.w = acc[nc][3]; }
        else     { z4.x = acc[nc][0];  z4.y = acc[nc][1];  z4.z = rx;         z4.w = ry;         }
        if (myE >= 0) {
            int col = nc * 8 + colbase;
            float4 yv = *(const float4*)(g_y + (size_t)myS * 64 + col);
            float4 v = make_float4(sigf(z4.x + yv.x), sigf(z4.y + yv.y),
                                   sigf(z4.z + yv.z), sigf(z4.w + yv.w));
            red4(xout + (size_t)myD * 64 + col, v);
        }
    }
}

// ---------------- readout ----------------
__global__ __launch_bounds__(TPB) void k_readout(
    const float* __restrict__ x, const float* __restrict__ Wread,
    const int* __restrict__ batch)
{
    __shared__ float Ws[TSTEPS * INF_ * 10];
    for (int i = threadIdx.x; i < TSTEPS * INF_ * 10; i += TPB) Ws[i] = Wread[i];
    __syncthreads();

    int n = blockIdx.x * blockDim.x + threadIdx.x;
    if (n >= NN) return;

    float xr[INF_];
    const float4* xp = (const float4*)(x + n * INF_);
    #pragma unroll
    for (int q = 0; q < INF_ / 4; q++) {
        float4 f = xp[q];
        xr[q*4+0] = f.x; xr[q*4+1] = f.y; xr[q*4+2] = f.z; xr[q*4+3] = f.w;
    }

    float accq[10];
    #pragma unroll
    for (int j = 0; j < 10; j++) accq[j] = 0.f;

    for (int t = 0; t < TSTEPS; t++) {
        float l[10];
        #pragma unroll
        for (int j = 0; j < 10; j++) l[j] = 0.f;
        const float* W = Ws + t * INF_ * 10;
        #pragma unroll 4
        for (int k = 0; k < INF_; k++) {
            float xv = xr[k];
            #pragma unroll
            for (int j = 0; j < 10; j++) l[j] += xv * W[k * 10 + j];
        }
        float m = l[0];
        #pragma unroll
        for (int j = 1; j < 10; j++) m = fmaxf(m, l[j]);
        float ssum = 0.f;
        #pragma unroll
        for (int j = 0; j < 10; j++) { l[j] = __expf(l[j] - m); ssum += l[j]; }
        float inv = 1.f / ssum;
        #pragma unroll
        for (int j = 0; j < 10; j++) accq[j] += l[j] * inv;
    }

    int g = batch[n];
    #pragma unroll
    for (int j = 0; j < 10; j++) atomicAdd(&g_pooled[g * 10 + j], accq[j]);
}

// ---------------- final MLP + graph-state reset ----------------
__global__ __launch_bounds__(TPB) void k_mlp(
    const float* __restrict__ fc1w, const float* __restrict__ fc1b,
    const float* __restrict__ fc2w, const float* __restrict__ fc2b,
    const float* __restrict__ fc3w, const float* __restrict__ fc3b,
    float* __restrict__ out)
{
    extern __shared__ float smf[];
    float* P  = smf;
    float* H1 = P + NG * 10;
    float* H2 = H1 + NG * 128;
    int tid = threadIdx.x;

    for (int i = tid; i < NG * 10; i += TPB) P[i] = g_pooled[i];
    __syncthreads();

    // reset device state so the graph is replay-invariant
    for (int i = tid; i < NN; i += TPB) { g_deg[i] = 0; g_ecur[i] = 0; }
    if (tid < NB) { g_nbcnt[tid] = 0; g_ebcnt[tid] = 0; g_ncur[tid] = 0; }
    for (int i = tid; i < NG * 10; i += TPB) g_pooled[i] = 0.f;

    for (int idx = tid; idx < NG * 128; idx += TPB) {
        int g = idx >> 7, j = idx & 127;
        float a = fc1b[j];
        #pragma unroll
        for (int k = 0; k < 10; k++) a += P[g * 10 + k] * fc1w[k * 128 + j];
        H1[idx] = a > 0.f ? a : 0.01f * a;
    }
    __syncthreads();

    for (int idx = tid; idx < NG * 64; idx += TPB) {
        int g = idx >> 6, j = idx & 63;
        float a = fc2b[j];
        #pragma unroll 8
        for (int k = 0; k < 128; k++) a += H1[g * 128 + k] * fc2w[k * 64 + j];
        H2[idx] = a > 0.f ? a : 0.01f * a;
    }
    __syncthreads();

    for (int g = tid; g < NG; g += TPB) {
        float a = fc3b[0];
        #pragma unroll 8
        for (int k = 0; k < 64; k++) a += H2[g * 64 + k] * fc3w[k];
        out[g] = a > 0.f ? a : 0.01f * a;
    }
}

// ---------------- launch ----------------
extern "C" void kernel_launch(void* const* d_in, const int* in_sizes, int n_in,
                              void* d_out, int out_size)
{
    const float* x     = (const float*)d_in[0];
    const float* ea    = (const float*)d_in[1];
    const float* Wmsg  = (const float*)d_in[2];
    const float* Wread = (const float*)d_in[3];
    const float* fc1w  = (const float*)d_in[4];
    const float* fc1b  = (const float*)d_in[5];
    const float* fc2w  = (const float*)d_in[6];
    const float* fc2b  = (const float*)d_in[7];
    const float* fc3w  = (const float*)d_in[8];
    const float* fc3b  = (const float*)d_in[9];
    const int*   ei    = (const int*)d_in[10];
    const int*   batch = (const int*)d_in[11];
    float* out = (float*)d_out;

    cudaFuncSetAttribute(k_node, cudaFuncAttributeMaxDynamicSharedMemorySize, NODE_SMEM);
    cudaFuncSetAttribute(k_edge, cudaFuncAttributeMaxDynamicSharedMemorySize, EDGE_SMEM);
    cudaFuncSetAttribute(k_mlp,  cudaFuncAttributeMaxDynamicSharedMemorySize, MLP_SMEM);

    void *pA = nullptr, *pB = nullptr;
    cudaGetSymbolAddress(&pA, g_xA);
    cudaGetSymbolAddress(&pB, g_xB);

    k_deg<<<(EE + TPB - 1) / TPB, TPB>>>(ei);                       // 0
    k_hist<<<(NN + TPB - 1) / TPB, TPB>>>();                        // 1
    k_start<<<1, 32>>>();                                           // 2
    k_nscatter<<<(NN + TPB - 1) / TPB, TPB>>>();                    // 3
    k_eptr<<<1, 1024>>>();                                          // 4
    k_escatter<<<(EE + TPB - 1) / TPB, TPB>>>(ei);                  // 5

    const float* xin = x;
    for (int t = 0; t < TSTEPS; t++) {
        const float* Wt = Wmsg + (size_t)t * NB * KD * INF_;
        float* xo = (t % 2 == 0) ? (float*)pB : (float*)pA;
        k_node<<<NTILEN, TPB, NODE_SMEM>>>(xin, Wt, xo);
        k_edge<<<NTILEE, TPB, EDGE_SMEM>>>(ea, ei, Wt, xo);
        xin = xo;
    }

    k_readout<<<(NN + TPB - 1) / TPB, TPB>>>(xin, Wread, batch);
    k_mlp<<<1, TPB, MLP_SMEM>>>(fc1w, fc1b, fc2w, fc2b, fc3w, fc3b, out);
}

// round 15
// speedup vs baseline: 1.3344x; 1.0564x over previous
#include <cuda_runtime.h>
#include <math.h>

// Problem constants
#define NN      20000
#define EE      160000
#define INF_    64
#define EC      16
#define KD      80
#define TSTEPS  4
#define NB      10
#define NG      64
#define TPB     256
#define TMN     64            // node-GEMM rows per tile
#define TME     128           // edge-GEMM rows per tile
#define NIS     68            // node smem dword row stride
#define EIS     20            // edge smem dword row stride
#define NTILEN  ((NN + TMN - 1) / TMN + NB)
#define NTILEE  ((EE + TME - 1) / TME + NB)

#define NODE_SMEM ((64*NIS + TMN*NIS) * 4 + TMN * 4)
#define EDGE_SMEM ((64*EIS + TME*EIS) * 4 + 3 * TME * 4)
#define MLP_SMEM  ((NG*10 + NG*128 + NG*64) * 4)

// ---------------- device scratch (zero at load; kept zeroed by k_mlp each call) ----------------
__device__ int   g_deg[NN];
__device__ int   g_cursor[NB];
__device__ int   g_ncursor[NB];
__device__ int   g_perm2[NB * EE];
__device__ int   g_nperm[NB * NN];
__device__ float g_y[NN * INF_];
__device__ float g_xA[NN * INF_];
__device__ float g_xB[NN * INF_];
__device__ float g_pooled[NG * 10];

// ---------------- helpers ----------------
__device__ __forceinline__ unsigned f2tf32(float f) {
    unsigned u; asm("cvt.rna.tf32.f32 %0, %1;" : "=r"(u) : "f"(f)); return u;
}
__device__ __forceinline__ void mma_tf32(float* c, unsigned a0, unsigned a1, unsigned a2, unsigned a3,
                                         unsigned b0, unsigned b1) {
    asm volatile("mma.sync.aligned.m16n8k8.row.col.f32.tf32.tf32.f32 "
                 "{%0,%1,%2,%3}, {%4,%5,%6,%7}, {%8,%9}, {%0,%1,%2,%3};"
                 : "+f"(c[0]), "+f"(c[1]), "+f"(c[2]), "+f"(c[3])
                 : "r"(a0), "r"(a1), "r"(a2), "r"(a3), "r"(b0), "r"(b1));
}
// sigmoid(x) = 0.5*tanh(x/2) + 0.5  (single MUFU via tanh.approx)
__device__ __forceinline__ float sigf(float x) {
    float t;
    float h = 0.5f * x;
    asm("tanh.approx.f32 %0, %1;" : "=f"(t) : "f"(h));
    return fmaf(0.5f, t, 0.5f);
}
__device__ __forceinline__ void red4(float* p, float4 v) {
    asm volatile("red.global.add.v4.f32 [%0], {%1, %2, %3, %4};"
                 :: "l"(p), "f"(v.x), "f"(v.y), "f"(v.z), "f"(v.w) : "memory");
}

// ---------------- preprocessing ----------------
__global__ void k_deg(const int* __restrict__ ei) {
    int e = blockIdx.x * blockDim.x + threadIdx.x;
    if (e < EE) atomicAdd(&g_deg[ei[e]], 1);
}

// fused node+edge two-level scatter (smem histograms, ranged global atomics)
__global__ void k_scatterBoth(const int* __restrict__ ei) {
    __shared__ int ecnt[NB], ern[NB];
    __shared__ int ncnt[NB], nrn[NB];
    int tid = threadIdx.x;
    if (tid < NB) { ecnt[tid] = 0; ncnt[tid] = 0; }
    __syncthreads();
    int idx = blockIdx.x * blockDim.x + tid;
    int eb = -1, epos = 0, nb = -1, npos = 0;
    if (idx < EE) {
        eb = min(g_deg[ei[idx]] + 1, NB) - 1;
        epos = atomicAdd(&ecnt[eb], 1);
    }
    if (idx < NN) {
        nb = min(g_deg[idx] + 1, NB) - 1;
        npos = atomicAdd(&ncnt[nb], 1);
    }
    __syncthreads();
    if (tid < NB) {
        ern[tid] = ecnt[tid] ? atomicAdd(&g_cursor[tid], ecnt[tid]) : 0;
        nrn[tid] = ncnt[tid] ? atomicAdd(&g_ncursor[tid], ncnt[tid]) : 0;
    }
    __syncthreads();
    if (idx < EE) g_perm2[eb * EE + ern[eb] + epos] = idx;
    if (idx < NN) g_nperm[nb * NN + nrn[nb] + npos] = idx;
}

// ---------------- node GEMM: y = x @ W_top[bucket(n)]; xout init = sigf(y) ----------------
// PDL: prologue (resolve, W stage, nperm) is independent of predecessor output;
// grid-dependency sync happens just before the x gather.
__global__ __launch_bounds__(TPB, 4) void k_node(
    const float* __restrict__ xin, const float* __restrict__ Wt,
    float* __restrict__ xout)
{
    cudaTriggerProgrammaticLaunchCompletion();

    extern __shared__ unsigned sm[];
    unsigned* Wts = sm;                   // [64][32 pairs] stride NIS
    unsigned* A   = sm + 64 * NIS;        // [TMN][32 pairs] stride NIS
    int* nidS = (int*)(A + TMN * NIS);

    const int tid = threadIdx.x;
    __shared__ int scnt[NB];
    __shared__ int s_bucket, s_loc, s_cnt;
    if (tid < NB) scnt[tid] = g_ncursor[tid];
    __syncthreads();
    if (tid == 0) {
        int acc = 0, b = -1, loc = 0, cnt = 0;
        #pragma unroll
        for (int i = 0; i < NB; i++) {
            int nt = (scnt[i] + TMN - 1) >> 6;
            if (b < 0 && (int)blockIdx.x < acc + nt) { b = i; loc = blockIdx.x - acc; cnt = scnt[i]; }
            acc += nt;
        }
        s_bucket = b; s_loc = loc; s_cnt = cnt;
    }
    __syncthreads();
    const int bucket = s_bucket;
    if (bucket < 0) return;
    const int cnt  = s_cnt;
    const int base = s_loc * TMN;

    const float* Wg = Wt + bucket * KD * 64;
    #pragma unroll
    for (int idx = tid; idx < 64 * 32; idx += TPB) {
        int c = idx & 63, p = idx >> 6;
        int kc = p >> 2, j = p & 3;
        int r0 = kc * 8 + j;
        uint2 u = make_uint2(f2tf32(Wg[r0 * 64 + c]), f2tf32(Wg[(r0 + 4) * 64 + c]));
        *(uint2*)(Wts + c * NIS + p * 2) = u;
    }
    if (tid < TMN)
        nidS[tid] = (base + tid < cnt) ? g_nperm[bucket * NN + base + tid] : -1;
    __syncthreads();

    // wait for predecessor (xin producer) before gathering x
    cudaGridDependencySynchronize();

    const float4* xin4 = (const float4*)xin;
    #pragma unroll
    for (int idx = tid; idx < TMN * 8; idx += TPB) {
        int r = idx >> 3, kc = idx & 7;
        int nid = nidS[r];
        float4 v0 = make_float4(0.f,0.f,0.f,0.f), v1 = v0;
        if (nid >= 0) { v0 = xin4[nid * 16 + kc * 2]; v1 = xin4[nid * 16 + kc * 2 + 1]; }
        unsigned* p = A + r * NIS + kc * 8;
        *(uint2*)(p + 0) = make_uint2(f2tf32(v0.x), f2tf32(v1.x));
        *(uint2*)(p + 2) = make_uint2(f2tf32(v0.y), f2tf32(v1.y));
        *(uint2*)(p + 4) = make_uint2(f2tf32(v0.z), f2tf32(v1.z));
        *(uint2*)(p + 6) = make_uint2(f2tf32(v0.w), f2tf32(v1.w));
    }
    __syncthreads();

    const int warp = tid >> 5, lane = tid & 31;
    const int g = lane >> 2, tg = lane & 3;
    const int rowbase = (warp >> 1) * 16;
    const int ch = warp & 1;

    float acc[4][4];
    #pragma unroll
    for (int n = 0; n < 4; n++)
        #pragma unroll
        for (int j = 0; j < 4; j++) acc[n][j] = 0.f;

    const unsigned* A0 = A + (rowbase + g) * NIS + tg * 2;
    const unsigned* A1 = A0 + 8 * NIS;
    const unsigned* Bb = Wts + (ch * 32 + g) * NIS + tg * 2;

    #pragma unroll
    for (int kc = 0; kc < 8; kc++) {
        const int ko = kc * 8;
        uint2 pa0 = *(const uint2*)(A0 + ko);
        uint2 pa1 = *(const uint2*)(A1 + ko);
        #pragma unroll
        for (int nc = 0; nc < 4; nc++) {
            uint2 pb = *(const uint2*)(Bb + nc * 8 * NIS + ko);
            mma_tf32(acc[nc], pa0.x, pa1.x, pa0.y, pa1.y, pb.x, pb.y);
        }
    }

    const int r0 = rowbase + g, r1 = r0 + 8;
    const int n0 = nidS[r0], n1 = nidS[r1];
    #pragma unroll
    for (int nc = 0; nc < 4; nc++) {
        int coff = ch * 32 + nc * 8 + tg * 2;
        if (n0 >= 0) {
            *(float2*)(g_y + n0 * 64 + coff) = make_float2(acc[nc][0], acc[nc][1]);
            *(float2*)(xout + n0 * 64 + coff) = make_float2(sigf(acc[nc][0]), sigf(acc[nc][1]));
        }
        if (n1 >= 0) {
            *(float2*)(g_y + n1 * 64 + coff) = make_float2(acc[nc][2], acc[nc][3]);
            *(float2*)(xout + n1 * 64 + coff) = make_float2(sigf(acc[nc][2]), sigf(acc[nc][3]));
        }
    }
}

// ---------------- edge GEMM + fused aggregation (v4 epilogue) ----------------
// PDL: everything through the MMA depends only on preprocessing/const inputs;
// grid-dependency sync happens just before the epilogue (reads g_y, reds xout).
__global__ __launch_bounds__(TPB, 4) void k_edge(
    const float* __restrict__ ea, const int* __restrict__ ei,
    const float* __restrict__ Wt, float* __restrict__ xout)
{
    cudaTriggerProgrammaticLaunchCompletion();

    extern __shared__ unsigned sm[];
    unsigned* Wts = sm;                   // [64][8 pairs] stride EIS
    unsigned* A   = sm + 64 * EIS;        // [TME][8 pairs] stride EIS
    int* eS   = (int*)(A + TME * EIS);
    int* srcS = eS + TME;
    int* dstS = srcS + TME;

    const int tid = threadIdx.x;
    __shared__ int scnt[NB];
    __shared__ int s_bucket, s_loc, s_cnt;
    if (tid < NB) scnt[tid] = g_cursor[tid];
    __syncthreads();
    if (tid == 0) {
        int acc = 0, b = -1, loc = 0, cnt = 0;
        #pragma unroll
        for (int i = 0; i < NB; i++) {
            int nt = (scnt[i] + TME - 1) >> 7;
            if (b < 0 && (int)blockIdx.x < acc + nt) { b = i; loc = blockIdx.x - acc; cnt = scnt[i]; }
            acc += nt;
        }
        s_bucket = b; s_loc = loc; s_cnt = cnt;
    }
    __syncthreads();
    const int bucket = s_bucket;
    if (bucket < 0) return;
    const int cnt  = s_cnt;
    const int base = s_loc * TME;

    // stage W_bot rows 64..79
    const float* Wg = Wt + bucket * KD * 64;
    #pragma unroll
    for (int idx = tid; idx < 64 * 8; idx += TPB) {
        int c = idx & 63, p = idx >> 6;
        int kc = p >> 2, j = p & 3;
        int r0 = 64 + kc * 8 + j;
        uint2 u = make_uint2(f2tf32(Wg[r0 * 64 + c]), f2tf32(Wg[(r0 + 4) * 64 + c]));
        *(uint2*)(Wts + c * EIS + p * 2) = u;
    }
    for (int r = tid; r < TME; r += TPB) {
        int e = -1, s = 0, d = -1;
        if (base + r < cnt) {
            e = g_perm2[bucket * EE + base + r];
            s = ei[e];
            d = ei[EE + e];
        }
        eS[r] = e; srcS[r] = s; dstS[r] = d;
    }
    __syncthreads();

    const float4* ea4 = (const float4*)ea;
    for (int idx = tid; idx < TME * 2; idx += TPB) {
        int r = idx >> 1, kc = idx & 1;
        int e = eS[r];
        float4 v0 = make_float4(0.f,0.f,0.f,0.f), v1 = v0;
        if (e >= 0) { v0 = ea4[e * 4 + kc * 2]; v1 = ea4[e * 4 + kc * 2 + 1]; }
        unsigned* p = A + r * EIS + kc * 8;
        *(uint2*)(p + 0) = make_uint2(f2tf32(v0.x), f2tf32(v1.x));
        *(uint2*)(p + 2) = make_uint2(f2tf32(v0.y), f2tf32(v1.y));
        *(uint2*)(p + 4) = make_uint2(f2tf32(v0.z), f2tf32(v1.z));
        *(uint2*)(p + 6) = make_uint2(f2tf32(v0.w), f2tf32(v1.w));
    }
    __syncthreads();

    const int warp = tid >> 5, lane = tid & 31;
    const int g = lane >> 2, tg = lane & 3;
    const int rowbase = warp * 16;

    float acc[8][4];
    #pragma unroll
    for (int n = 0; n < 8; n++)
        #pragma unroll
        for (int j = 0; j < 4; j++) acc[n][j] = 0.f;

    const unsigned* A0 = A + (rowbase + g) * EIS + tg * 2;
    const unsigned* A1 = A0 + 8 * EIS;
    const unsigned* Bb = Wts + g * EIS + tg * 2;

    #pragma unroll
    for (int kc = 0; kc < 2; kc++) {
        const int ko = kc * 8;
        uint2 pa0 = *(const uint2*)(A0 + ko);
        uint2 pa1 = *(const uint2*)(A1 + ko);
        #pragma unroll
        for (int nc = 0; nc < 8; nc++) {
            uint2 pb = *(const uint2*)(Bb + nc * 8 * EIS + ko);
            mma_tf32(acc[nc], pa0.x, pa1.x, pa0.y, pa1.y, pb.x, pb.y);
        }
    }

    // wait for predecessor (k_node: g_y + xout init) before the epilogue
    cudaGridDependencySynchronize();

    // epilogue: lane-pair shuffle -> 4 contiguous cols per lane; v4 gather + v4 reduction
    const int r0 = rowbase + g, r1 = r0 + 8;
    const bool odd = tg & 1;
    const int myE = odd ? eS[r1]   : eS[r0];
    const int myS = odd ? srcS[r1] : srcS[r0];
    const int myD = odd ? dstS[r1] : dstS[r0];
    const int colbase = (tg & ~1) * 2;
    #pragma unroll
    for (int nc = 0; nc < 8; nc++) {
        float sx = odd ? acc[nc][0] : acc[nc][2];
        float sy = odd ? acc[nc][1] : acc[nc][3];
        float rx = __shfl_xor_sync(0xffffffffu, sx, 1);
        float ry = __shfl_xor_sync(0xffffffffu, sy, 1);
        float4 z4;
        if (odd) { z4.x = rx;          z4.y = ry;          z4.z = acc[nc][2]; z4.w = acc[nc][3]; }
        else     { z4.x = acc[nc][0];  z4.y = acc[nc][1];  z4.z = rx;         z4.w = ry;         }
        if (myE >= 0) {
            int col = nc * 8 + colbase;
            float4 yv = *(const float4*)(g_y + (size_t)myS * 64 + col);
            float4 v = make_float4(sigf(z4.x + yv.x), sigf(z4.y + yv.y),
                                   sigf(z4.z + yv.z), sigf(z4.w + yv.w));
            red4(xout + (size_t)myD * 64 + col, v);
        }
    }
}

// ---------------- readout ----------------
__global__ __launch_bounds__(TPB) void k_readout(
    const float* __restrict__ x, const float* __restrict__ Wread,
    const int* __restrict__ batch)
{
    __shared__ float Ws[TSTEPS * INF_ * 10];
    for (int i = threadIdx.x; i < TSTEPS * INF_ * 10; i += TPB) Ws[i] = Wread[i];
    __syncthreads();

    int n = blockIdx.x * blockDim.x + threadIdx.x;
    if (n >= NN) return;

    float xr[INF_];
    const float4* xp = (const float4*)(x + n * INF_);
    #pragma unroll
    for (int q = 0; q < INF_ / 4; q++) {
        float4 f = xp[q];
        xr[q*4+0] = f.x; xr[q*4+1] = f.y; xr[q*4+2] = f.z; xr[q*4+3] = f.w;
    }

    float accq[10];
    #pragma unroll
    for (int j = 0; j < 10; j++) accq[j] = 0.f;

    for (int t = 0; t < TSTEPS; t++) {
        float l[10];
        #pragma unroll
        for (int j = 0; j < 10; j++) l[j] = 0.f;
        const float* W = Ws + t * INF_ * 10;
        #pragma unroll 4
        for (int k = 0; k < INF_; k++) {
            float xv = xr[k];
            #pragma unroll
            for (int j = 0; j < 10; j++) l[j] += xv * W[k * 10 + j];
        }
        float m = l[0];
        #pragma unroll
        for (int j = 1; j < 10; j++) m = fmaxf(m, l[j]);
        float ssum = 0.f;
        #pragma unroll
        for (int j = 0; j < 10; j++) { l[j] = __expf(l[j] - m); ssum += l[j]; }
        float inv = 1.f / ssum;
        #pragma unroll
        for (int j = 0; j < 10; j++) accq[j] += l[j] * inv;
    }

    int g = batch[n];
    #pragma unroll
    for (int j = 0; j < 10; j++) atomicAdd(&g_pooled[g * 10 + j], accq[j]);
}

// ---------------- final MLP + graph-state reset ----------------
__global__ __launch_bounds__(TPB) void k_mlp(
    const float* __restrict__ fc1w, const float* __restrict__ fc1b,
    const float* __restrict__ fc2w, const float* __restrict__ fc2b,
    const float* __restrict__ fc3w, const float* __restrict__ fc3b,
    float* __restrict__ out)
{
    extern __shared__ float smf[];
    float* P  = smf;
    float* H1 = P + NG * 10;
    float* H2 = H1 + NG * 128;
    int tid = threadIdx.x;

    for (int i = tid; i < NG * 10; i += TPB) P[i] = g_pooled[i];
    __syncthreads();

    // reset device state so the graph is replay-invariant
    for (int i = tid; i < NN; i += TPB) g_deg[i] = 0;
    if (tid < NB) { g_cursor[tid] = 0; g_ncursor[tid] = 0; }
    for (int i = tid; i < NG * 10; i += TPB) g_pooled[i] = 0.f;

    for (int idx = tid; idx < NG * 128; idx += TPB) {
        int g = idx >> 7, j = idx & 127;
        float a = fc1b[j];
        #pragma unroll
        for (int k = 0; k < 10; k++) a += P[g * 10 + k] * fc1w[k * 128 + j];
        H1[idx] = a > 0.f ? a : 0.01f * a;
    }
    __syncthreads();

    for (int idx = tid; idx < NG * 64; idx += TPB) {
        int g = idx >> 6, j = idx & 63;
        float a = fc2b[j];
        #pragma unroll 8
        for (int k = 0; k < 128; k++) a += H1[g * 128 + k] * fc2w[k * 64 + j];
        H2[idx] = a > 0.f ? a : 0.01f * a;
    }
    __syncthreads();

    for (int g = tid; g < NG; g += TPB) {
        float a = fc3b[0];
        #pragma unroll 8
        for (int k = 0; k < 64; k++) a += H2[g * 64 + k] * fc3w[k];
        out[g] = a > 0.f ? a : 0.01f * a;
    }
}

// ---------------- launch ----------------
extern "C" void kernel_launch(void* const* d_in, const int* in_sizes, int n_in,
                              void* d_out, int out_size)
{
    const float* x     = (const float*)d_in[0];
    const float* ea    = (const float*)d_in[1];
    const float* Wmsg  = (const float*)d_in[2];
    const float* Wread = (const float*)d_in[3];
    const float* fc1w  = (const float*)d_in[4];
    const float* fc1b  = (const float*)d_in[5];
    const float* fc2w  = (const float*)d_in[6];
    const float* fc2b  = (const float*)d_in[7];
    const float* fc3w  = (const float*)d_in[8];
    const float* fc3b  = (const float*)d_in[9];
    const int*   ei    = (const int*)d_in[10];
    const int*   batch = (const int*)d_in[11];
    float* out = (float*)d_out;

    cudaFuncSetAttribute(k_node, cudaFuncAttributeMaxDynamicSharedMemorySize, NODE_SMEM);
    cudaFuncSetAttribute(k_edge, cudaFuncAttributeMaxDynamicSharedMemorySize, EDGE_SMEM);
    cudaFuncSetAttribute(k_mlp,  cudaFuncAttributeMaxDynamicSharedMemorySize, MLP_SMEM);

    void *pA = nullptr, *pB = nullptr;
    cudaGetSymbolAddress(&pA, g_xA);
    cudaGetSymbolAddress(&pB, g_xB);

    k_deg<<<(EE + TPB - 1) / TPB, TPB>>>(ei);
    k_scatterBoth<<<(EE + TPB - 1) / TPB, TPB>>>(ei);

    // PDL launch config (secondary may start while predecessor is running)
    cudaLaunchAttribute pdlAttr[1];
    pdlAttr[0].id = cudaLaunchAttributeProgrammaticStreamSerialization;
    pdlAttr[0].val.programmaticStreamSerializationAllowed = 1;

    cudaLaunchConfig_t cfgNode = {};
    cfgNode.gridDim = dim3(NTILEN);
    cfgNode.blockDim = dim3(TPB);
    cfgNode.dynamicSmemBytes = NODE_SMEM;
    cfgNode.stream = 0;
    cfgNode.attrs = pdlAttr;
    cfgNode.numAttrs = 1;

    cudaLaunchConfig_t cfgEdge = {};
    cfgEdge.gridDim = dim3(NTILEE);
    cfgEdge.blockDim = dim3(TPB);
    cfgEdge.dynamicSmemBytes = EDGE_SMEM;
    cfgEdge.stream = 0;
    cfgEdge.attrs = pdlAttr;
    cfgEdge.numAttrs = 1;

    const float* xin = x;
    for (int t = 0; t < TSTEPS; t++) {
        const float* Wt = Wmsg + (size_t)t * NB * KD * INF_;
        float* xo = (t % 2 == 0) ? (float*)pB : (float*)pA;
        if (t == 0) {
            // predecessor (k_scatterBoth) writes g_ncursor which k_node reads
            // pre-sync -> must fully serialize; plain launch.
            k_node<<<NTILEN, TPB, NODE_SMEM>>>(xin, Wt, xo);
        } else {
            cudaLaunchKernelEx(&cfgNode, k_node, xin, Wt, xo);
        }
        cudaLaunchKernelEx(&cfgEdge, k_edge, ea, ei, Wt, xo);
        xin = xo;
    }

    k_readout<<<(NN + TPB - 1) / TPB, TPB>>>(xin, Wread, batch);
    k_mlp<<<1, TPB, MLP_SMEM>>>(fc1w, fc1b, fc2w, fc2b, fc3w, fc3b, out);
}

// round 16
// speedup vs baseline: 1.3467x; 1.0092x over previous
#include <cuda_runtime.h>
#include <math.h>

// Problem constants
#define NN      20000
#define EE      160000
#define INF_    64
#define EC      16
#define KD      80
#define TSTEPS  4
#define NB      10
#define NG      64
#define TPB     256
#define TMN     64            // node-GEMM rows per tile
#define TME     128           // edge-GEMM rows per tile
#define NIS     68            // node smem dword row stride
#define EIS     20            // edge smem dword row stride
#define NTILEN  ((NN + TMN - 1) / TMN + NB)
#define NTILEE  ((EE + TME - 1) / TME + NB)

#define NODE_SMEM ((64*NIS + TMN*NIS) * 4 + TMN * 4)
#define EDGE_SMEM ((64*EIS + TME*EIS) * 4 + 3 * TME * 4)
#define MLP_SMEM  ((NG*10 + NG*128 + NG*64) * 4)

// ---------------- device scratch (zero at load; kept zeroed by k_mlp each call) ----------------
__device__ int   g_deg[NN];
__device__ int   g_cursor[NB];
__device__ int   g_ncursor[NB];
__device__ int   g_perm2[NB * EE];
__device__ int   g_nperm[NB * NN];
__device__ float g_y[NN * INF_];
__device__ float g_xA[NN * INF_];
__device__ float g_xB[NN * INF_];
__device__ float g_pooled[NG * 10];

// ---------------- helpers ----------------
__device__ __forceinline__ unsigned f2tf32(float f) {
    unsigned u; asm("cvt.rna.tf32.f32 %0, %1;" : "=r"(u) : "f"(f)); return u;
}
__device__ __forceinline__ void mma_tf32(float* c, unsigned a0, unsigned a1, unsigned a2, unsigned a3,
                                         unsigned b0, unsigned b1) {
    asm volatile("mma.sync.aligned.m16n8k8.row.col.f32.tf32.tf32.f32 "
                 "{%0,%1,%2,%3}, {%4,%5,%6,%7}, {%8,%9}, {%0,%1,%2,%3};"
                 : "+f"(c[0]), "+f"(c[1]), "+f"(c[2]), "+f"(c[3])
                 : "r"(a0), "r"(a1), "r"(a2), "r"(a3), "r"(b0), "r"(b1));
}
// sigmoid(x) = 0.5*tanh(x/2) + 0.5  (single MUFU via tanh.approx)
__device__ __forceinline__ float sigf(float x) {
    float t;
    float h = 0.5f * x;
    asm("tanh.approx.f32 %0, %1;" : "=f"(t) : "f"(h));
    return fmaf(0.5f, t, 0.5f);
}
__device__ __forceinline__ void red4(float* p, float4 v) {
    asm volatile("red.global.add.v4.f32 [%0], {%1, %2, %3, %4};"
                 :: "l"(p), "f"(v.x), "f"(v.y), "f"(v.z), "f"(v.w) : "memory");
}

// ---------------- preprocessing ----------------
__global__ void k_deg(const int* __restrict__ ei) {
    int e = blockIdx.x * blockDim.x + threadIdx.x;
    if (e < EE) atomicAdd(&g_deg[ei[e]], 1);
}

// fused node+edge two-level scatter (smem histograms, ranged global atomics)
__global__ void k_scatterBoth(const int* __restrict__ ei) {
    __shared__ int ecnt[NB], ern[NB];
    __shared__ int ncnt[NB], nrn[NB];
    int tid = threadIdx.x;
    if (tid < NB) { ecnt[tid] = 0; ncnt[tid] = 0; }
    __syncthreads();
    int idx = blockIdx.x * blockDim.x + tid;
    int eb = -1, epos = 0, nb = -1, npos = 0;
    if (idx < EE) {
        eb = min(g_deg[ei[idx]] + 1, NB) - 1;
        epos = atomicAdd(&ecnt[eb], 1);
    }
    if (idx < NN) {
        nb = min(g_deg[idx] + 1, NB) - 1;
        npos = atomicAdd(&ncnt[nb], 1);
    }
    __syncthreads();
    if (tid < NB) {
        ern[tid] = ecnt[tid] ? atomicAdd(&g_cursor[tid], ecnt[tid]) : 0;
        nrn[tid] = ncnt[tid] ? atomicAdd(&g_ncursor[tid], ncnt[tid]) : 0;
    }
    __syncthreads();
    if (idx < EE) g_perm2[eb * EE + ern[eb] + epos] = idx;
    if (idx < NN) g_nperm[nb * NN + nrn[nb] + npos] = idx;
}

// ---------------- node GEMM: y = x @ W_top[bucket(n)]; xout init = sigf(y) ----------------
// PDL: prologue independent of predecessor output; sync just before the x gather.
__global__ __launch_bounds__(TPB, 4) void k_node(
    const float* __restrict__ xin, const float* __restrict__ Wt,
    float* __restrict__ xout)
{
    cudaTriggerProgrammaticLaunchCompletion();

    extern __shared__ unsigned sm[];
    unsigned* Wts = sm;                   // [64][32 pairs] stride NIS
    unsigned* A   = sm + 64 * NIS;        // [TMN][32 pairs] stride NIS
    int* nidS = (int*)(A + TMN * NIS);

    const int tid = threadIdx.x;
    __shared__ int scnt[NB];
    __shared__ int s_bucket, s_loc, s_cnt;
    if (tid < NB) scnt[tid] = g_ncursor[tid];
    __syncthreads();
    if (tid == 0) {
        int acc = 0, b = -1, loc = 0, cnt = 0;
        #pragma unroll
        for (int i = 0; i < NB; i++) {
            int nt = (scnt[i] + TMN - 1) >> 6;
            if (b < 0 && (int)blockIdx.x < acc + nt) { b = i; loc = blockIdx.x - acc; cnt = scnt[i]; }
            acc += nt;
        }
        s_bucket = b; s_loc = loc; s_cnt = cnt;
    }
    __syncthreads();
    const int bucket = s_bucket;
    if (bucket < 0) return;
    const int cnt  = s_cnt;
    const int base = s_loc * TMN;

    const float* Wg = Wt + bucket * KD * 64;
    #pragma unroll
    for (int idx = tid; idx < 64 * 32; idx += TPB) {
        int c = idx & 63, p = idx >> 6;
        int kc = p >> 2, j = p & 3;
        int r0 = kc * 8 + j;
        uint2 u = make_uint2(f2tf32(Wg[r0 * 64 + c]), f2tf32(Wg[(r0 + 4) * 64 + c]));
        *(uint2*)(Wts + c * NIS + p * 2) = u;
    }
    if (tid < TMN)
        nidS[tid] = (base + tid < cnt) ? g_nperm[bucket * NN + base + tid] : -1;
    __syncthreads();

    // wait for predecessor (xin producer) before gathering x
    cudaGridDependencySynchronize();

    const float4* xin4 = (const float4*)xin;
    #pragma unroll
    for (int idx = tid; idx < TMN * 8; idx += TPB) {
        int r = idx >> 3, kc = idx & 7;
        int nid = nidS[r];
        float4 v0 = make_float4(0.f,0.f,0.f,0.f), v1 = v0;
        if (nid >= 0) { v0 = xin4[nid * 16 + kc * 2]; v1 = xin4[nid * 16 + kc * 2 + 1]; }
        unsigned* p = A + r * NIS + kc * 8;
        *(uint2*)(p + 0) = make_uint2(f2tf32(v0.x), f2tf32(v1.x));
        *(uint2*)(p + 2) = make_uint2(f2tf32(v0.y), f2tf32(v1.y));
        *(uint2*)(p + 4) = make_uint2(f2tf32(v0.z), f2tf32(v1.z));
        *(uint2*)(p + 6) = make_uint2(f2tf32(v0.w), f2tf32(v1.w));
    }
    __syncthreads();

    const int warp = tid >> 5, lane = tid & 31;
    const int g = lane >> 2, tg = lane & 3;
    const int rowbase = (warp >> 1) * 16;
    const int ch = warp & 1;

    float acc[4][4];
    #pragma unroll
    for (int n = 0; n < 4; n++)
        #pragma unroll
        for (int j = 0; j < 4; j++) acc[n][j] = 0.f;

    const unsigned* A0 = A + (rowbase + g) * NIS + tg * 2;
    const unsigned* A1 = A0 + 8 * NIS;
    const unsigned* Bb = Wts + (ch * 32 + g) * NIS + tg * 2;

    #pragma unroll
    for (int kc = 0; kc < 8; kc++) {
        const int ko = kc * 8;
        uint2 pa0 = *(const uint2*)(A0 + ko);
        uint2 pa1 = *(const uint2*)(A1 + ko);
        #pragma unroll
        for (int nc = 0; nc < 4; nc++) {
            uint2 pb = *(const uint2*)(Bb + nc * 8 * NIS + ko);
            mma_tf32(acc[nc], pa0.x, pa1.x, pa0.y, pa1.y, pb.x, pb.y);
        }
    }

    const int r0 = rowbase + g, r1 = r0 + 8;
    const int n0 = nidS[r0], n1 = nidS[r1];
    #pragma unroll
    for (int nc = 0; nc < 4; nc++) {
        int coff = ch * 32 + nc * 8 + tg * 2;
        if (n0 >= 0) {
            *(float2*)(g_y + n0 * 64 + coff) = make_float2(acc[nc][0], acc[nc][1]);
            *(float2*)(xout + n0 * 64 + coff) = make_float2(sigf(acc[nc][0]), sigf(acc[nc][1]));
        }
        if (n1 >= 0) {
            *(float2*)(g_y + n1 * 64 + coff) = make_float2(acc[nc][2], acc[nc][3]);
            *(float2*)(xout + n1 * 64 + coff) = make_float2(sigf(acc[nc][2]), sigf(acc[nc][3]));
        }
    }
}

// ---------------- edge GEMM + fused aggregation (v4 epilogue) ----------------
// PDL: everything through the MMA depends only on preprocessing/const inputs;
// sync just before the epilogue. Occupancy raised to 5 blocks/SM (reg target 51).
__global__ __launch_bounds__(TPB, 5) void k_edge(
    const float* __restrict__ ea, const int* __restrict__ ei,
    const float* __restrict__ Wt, float* __restrict__ xout)
{
    cudaTriggerProgrammaticLaunchCompletion();

    extern __shared__ unsigned sm[];
    unsigned* Wts = sm;                   // [64][8 pairs] stride EIS
    unsigned* A   = sm + 64 * EIS;        // [TME][8 pairs] stride EIS
    int* eS   = (int*)(A + TME * EIS);
    int* srcS = eS + TME;
    int* dstS = srcS + TME;

    const int tid = threadIdx.x;
    __shared__ int scnt[NB];
    __shared__ int s_bucket, s_loc, s_cnt;
    if (tid < NB) scnt[tid] = g_cursor[tid];
    __syncthreads();
    if (tid == 0) {
        int acc = 0, b = -1, loc = 0, cnt = 0;
        #pragma unroll
        for (int i = 0; i < NB; i++) {
            int nt = (scnt[i] + TME - 1) >> 7;
            if (b < 0 && (int)blockIdx.x < acc + nt) { b = i; loc = blockIdx.x - acc; cnt = scnt[i]; }
            acc += nt;
        }
        s_bucket = b; s_loc = loc; s_cnt = cnt;
    }
    __syncthreads();
    const int bucket = s_bucket;
    if (bucket < 0) return;
    const int cnt  = s_cnt;
    const int base = s_loc * TME;

    // stage W_bot rows 64..79
    const float* Wg = Wt + bucket * KD * 64;
    #pragma unroll
    for (int idx = tid; idx < 64 * 8; idx += TPB) {
        int c = idx & 63, p = idx >> 6;
        int kc = p >> 2, j = p & 3;
        int r0 = 64 + kc * 8 + j;
        uint2 u = make_uint2(f2tf32(Wg[r0 * 64 + c]), f2tf32(Wg[(r0 + 4) * 64 + c]));
        *(uint2*)(Wts + c * EIS + p * 2) = u;
    }
    for (int r = tid; r < TME; r += TPB) {
        int e = -1, s = 0, d = -1;
        if (base + r < cnt) {
            e = g_perm2[bucket * EE + base + r];
            s = ei[e];
            d = ei[EE + e];
        }
        eS[r] = e; srcS[r] = s; dstS[r] = d;
    }
    __syncthreads();

    const float4* ea4 = (const float4*)ea;
    for (int idx = tid; idx < TME * 2; idx += TPB) {
        int r = idx >> 1, kc = idx & 1;
        int e = eS[r];
        float4 v0 = make_float4(0.f,0.f,0.f,0.f), v1 = v0;
        if (e >= 0) { v0 = ea4[e * 4 + kc * 2]; v1 = ea4[e * 4 + kc * 2 + 1]; }
        unsigned* p = A + r * EIS + kc * 8;
        *(uint2*)(p + 0) = make_uint2(f2tf32(v0.x), f2tf32(v1.x));
        *(uint2*)(p + 2) = make_uint2(f2tf32(v0.y), f2tf32(v1.y));
        *(uint2*)(p + 4) = make_uint2(f2tf32(v0.z), f2tf32(v1.z));
        *(uint2*)(p + 6) = make_uint2(f2tf32(v0.w), f2tf32(v1.w));
    }
    __syncthreads();

    const int warp = tid >> 5, lane = tid & 31;
    const int g = lane >> 2, tg = lane & 3;
    const int rowbase = warp * 16;

    float acc[8][4];
    #pragma unroll
    for (int n = 0; n < 8; n++)
        #pragma unroll
        for (int j = 0; j < 4; j++) acc[n][j] = 0.f;

    const unsigned* A0 = A + (rowbase + g) * EIS + tg * 2;
    const unsigned* A1 = A0 + 8 * EIS;
    const unsigned* Bb = Wts + g * EIS + tg * 2;

    #pragma unroll
    for (int kc = 0; kc < 2; kc++) {
        const int ko = kc * 8;
        uint2 pa0 = *(const uint2*)(A0 + ko);
        uint2 pa1 = *(const uint2*)(A1 + ko);
        #pragma unroll
        for (int nc = 0; nc < 8; nc++) {
            uint2 pb = *(const uint2*)(Bb + nc * 8 * EIS + ko);
            mma_tf32(acc[nc], pa0.x, pa1.x, pa0.y, pa1.y, pb.x, pb.y);
        }
    }

    // wait for predecessor (k_node: g_y + xout init) before the epilogue
    cudaGridDependencySynchronize();

    // epilogue: lane-pair shuffle -> 4 contiguous cols per lane; v4 gather + v4 reduction
    const int r0 = rowbase + g, r1 = r0 + 8;
    const bool odd = tg & 1;
    const int myE = odd ? eS[r1]   : eS[r0];
    const int myS = odd ? srcS[r1] : srcS[r0];
    const int myD = odd ? dstS[r1] : dstS[r0];
    const int colbase = (tg & ~1) * 2;
    #pragma unroll
    for (int nc = 0; nc < 8; nc++) {
        float sx = odd ? acc[nc][0] : acc[nc][2];
        float sy = odd ? acc[nc][1] : acc[nc][3];
        float rx = __shfl_xor_sync(0xffffffffu, sx, 1);
        float ry = __shfl_xor_sync(0xffffffffu, sy, 1);
        float4 z4;
        if (odd) { z4.x = rx;          z4.y = ry;          z4.z = acc[nc][2]; z4.w = acc[nc][3]; }
        else     { z4.x = acc[nc][0];  z4.y = acc[nc][1];  z4.z = rx;         z4.w = ry;         }
        if (myE >= 0) {
            int col = nc * 8 + colbase;
            float4 yv = *(const float4*)(g_y + (size_t)myS * 64 + col);
            float4 v = make_float4(sigf(z4.x + yv.x), sigf(z4.y + yv.y),
                                   sigf(z4.z + yv.z), sigf(z4.w + yv.w));
            red4(xout + (size_t)myD * 64 + col, v);
        }
    }
}

// ---------------- readout (PDL: W staging pre-sync) ----------------
__global__ __launch_bounds__(TPB) void k_readout(
    const float* __restrict__ x, const float* __restrict__ Wread,
    const int* __restrict__ batch)
{
    cudaTriggerProgrammaticLaunchCompletion();

    __shared__ float Ws[TSTEPS * INF_ * 10];
    for (int i = threadIdx.x; i < TSTEPS * INF_ * 10; i += TPB) Ws[i] = Wread[i];
    __syncthreads();

    cudaGridDependencySynchronize();

    int n = blockIdx.x * blockDim.x + threadIdx.x;
    if (n >= NN) return;

    float xr[INF_];
    const float4* xp = (const float4*)(x + n * INF_);
    #pragma unroll
    for (int q = 0; q < INF_ / 4; q++) {
        float4 f = xp[q];
        xr[q*4+0] = f.x; xr[q*4+1] = f.y; xr[q*4+2] = f.z; xr[q*4+3] = f.w;
    }

    float accq[10];
    #pragma unroll
    for (int j = 0; j < 10; j++) accq[j] = 0.f;

    for (int t = 0; t < TSTEPS; t++) {
        float l[10];
        #pragma unroll
        for (int j = 0; j < 10; j++) l[j] = 0.f;
        const float* W = Ws + t * INF_ * 10;
        #pragma unroll 4
        for (int k = 0; k < INF_; k++) {
            float xv = xr[k];
            #pragma unroll
            for (int j = 0; j < 10; j++) l[j] += xv * W[k * 10 + j];
        }
        float m = l[0];
        #pragma unroll
        for (int j = 1; j < 10; j++) m = fmaxf(m, l[j]);
        float ssum = 0.f;
        #pragma unroll
        for (int j = 0; j < 10; j++) { l[j] = __expf(l[j] - m); ssum += l[j]; }
        float inv = 1.f / ssum;
        #pragma unroll
        for (int j = 0; j < 10; j++) accq[j] += l[j] * inv;
    }

    int g = batch[n];
    #pragma unroll
    for (int j = 0; j < 10; j++) atomicAdd(&g_pooled[g * 10 + j], accq[j]);
}

// ---------------- final MLP + graph-state reset ----------------
__global__ __launch_bounds__(TPB) void k_mlp(
    const float* __restrict__ fc1w, const float* __restrict__ fc1b,
    const float* __restrict__ fc2w, const float* __restrict__ fc2b,
    const float* __restrict__ fc3w, const float* __restrict__ fc3b,
    float* __restrict__ out)
{
    extern __shared__ float smf[];
    float* P  = smf;
    float* H1 = P + NG * 10;
    float* H2 = H1 + NG * 128;
    int tid = threadIdx.x;

    for (int i = tid; i < NG * 10; i += TPB) P[i] = g_pooled[i];
    __syncthreads();

    // reset device state so the graph is replay-invariant
    for (int i = tid; i < NN; i += TPB) g_deg[i] = 0;
    if (tid < NB) { g_cursor[tid] = 0; g_ncursor[tid] = 0; }
    for (int i = tid; i < NG * 10; i += TPB) g_pooled[i] = 0.f;

    for (int idx = tid; idx < NG * 128; idx += TPB) {
        int g = idx >> 7, j = idx & 127;
        float a = fc1b[j];
        #pragma unroll
        for (int k = 0; k < 10; k++) a += P[g * 10 + k] * fc1w[k * 128 + j];
        H1[idx] = a > 0.f ? a : 0.01f * a;
    }
    __syncthreads();

    for (int idx = tid; idx < NG * 64; idx += TPB) {
        int g = idx >> 6, j = idx & 63;
        float a = fc2b[j];
        #pragma unroll 8
        for (int k = 0; k < 128; k++) a += H1[g * 128 + k] * fc2w[k * 64 + j];
        H2[idx] = a > 0.f ? a : 0.01f * a;
    }
    __syncthreads();

    for (int g = tid; g < NG; g += TPB) {
        float a = fc3b[0];
        #pragma unroll 8
        for (int k = 0; k < 64; k++) a += H2[g * 64 + k] * fc3w[k];
        out[g] = a > 0.f ? a : 0.01f * a;
    }
}

// ---------------- launch ----------------
extern "C" void kernel_launch(void* const* d_in, const int* in_sizes, int n_in,
                              void* d_out, int out_size)
{
    const float* x     = (const float*)d_in[0];
    const float* ea    = (const float*)d_in[1];
    const float* Wmsg  = (const float*)d_in[2];
    const float* Wread = (const float*)d_in[3];
    const float* fc1w  = (const float*)d_in[4];
    const float* fc1b  = (const float*)d_in[5];
    const float* fc2w  = (const float*)d_in[6];
    const float* fc2b  = (const float*)d_in[7];
    const float* fc3w  = (const float*)d_in[8];
    const float* fc3b  = (const float*)d_in[9];
    const int*   ei    = (const int*)d_in[10];
    const int*   batch = (const int*)d_in[11];
    float* out = (float*)d_out;

    cudaFuncSetAttribute(k_node, cudaFuncAttributeMaxDynamicSharedMemorySize, NODE_SMEM);
    cudaFuncSetAttribute(k_edge, cudaFuncAttributeMaxDynamicSharedMemorySize, EDGE_SMEM);
    cudaFuncSetAttribute(k_mlp,  cudaFuncAttributeMaxDynamicSharedMemorySize, MLP_SMEM);

    void *pA = nullptr, *pB = nullptr;
    cudaGetSymbolAddress(&pA, g_xA);
    cudaGetSymbolAddress(&pB, g_xB);

    k_deg<<<(EE + TPB - 1) / TPB, TPB>>>(ei);
    k_scatterBoth<<<(EE + TPB - 1) / TPB, TPB>>>(ei);

    // PDL launch config
    cudaLaunchAttribute pdlAttr[1];
    pdlAttr[0].id = cudaLaunchAttributeProgrammaticStreamSerialization;
    pdlAttr[0].val.programmaticStreamSerializationAllowed = 1;

    cudaLaunchConfig_t cfgNode = {};
    cfgNode.gridDim = dim3(NTILEN);
    cfgNode.blockDim = dim3(TPB);
    cfgNode.dynamicSmemBytes = NODE_SMEM;
    cfgNode.stream = 0;
    cfgNode.attrs = pdlAttr;
    cfgNode.numAttrs = 1;

    cudaLaunchConfig_t cfgEdge = {};
    cfgEdge.gridDim = dim3(NTILEE);
    cfgEdge.blockDim = dim3(TPB);
    cfgEdge.dynamicSmemBytes = EDGE_SMEM;
    cfgEdge.stream = 0;
    cfgEdge.attrs = pdlAttr;
    cfgEdge.numAttrs = 1;

    cudaLaunchConfig_t cfgRead = {};
    cfgRead.gridDim = dim3((NN + TPB - 1) / TPB);
    cfgRead.blockDim = dim3(TPB);
    cfgRead.dynamicSmemBytes = 0;
    cfgRead.stream = 0;
    cfgRead.attrs = pdlAttr;
    cfgRead.numAttrs = 1;

    const float* xin = x;
    for (int t = 0; t < TSTEPS; t++) {
        const float* Wt = Wmsg + (size_t)t * NB * KD * INF_;
        float* xo = (t % 2 == 0) ? (float*)pB : (float*)pA;
        if (t == 0) {
            // k_node reads g_ncursor (written by immediate predecessor) pre-sync -> serialize.
            k_node<<<NTILEN, TPB, NODE_SMEM>>>(xin, Wt, xo);
        } else {
            cudaLaunchKernelEx(&cfgNode, k_node, xin, Wt, xo);
        }
        cudaLaunchKernelEx(&cfgEdge, k_edge, ea, ei, Wt, xo);
        xin = xo;
    }

    cudaLaunchKernelEx(&cfgRead, k_readout, xin, Wread, batch);
    k_mlp<<<1, TPB, MLP_SMEM>>>(fc1w, fc1b, fc2w, fc2b, fc3w, fc3b, out);
}

// round 17
// speedup vs baseline: 1.3715x; 1.0184x over previous
#include <cuda_runtime.h>
#include <math.h>

// Problem constants
#define NN      20000
#define EE      160000
#define INF_    64
#define EC      16
#define KD      80
#define TSTEPS  4
#define NB      10
#define NG      64
#define TPB     256
#define TPBE    512           // k_edge threads (paired-warp mapping)
#define TMN     64            // node-GEMM rows per tile
#define TME     128           // edge-GEMM rows per tile
#define NIS     68            // node smem dword row stride
#define EIS     20            // edge smem dword row stride
#define NTILEN  ((NN + TMN - 1) / TMN + NB)
#define NTILEE  ((EE + TME - 1) / TME + NB)

#define NODE_SMEM ((64*NIS + TMN*NIS) * 4 + TMN * 4)
#define EDGE_SMEM ((64*EIS + TME*EIS) * 4 + 3 * TME * 4)
#define MLP_SMEM  ((NG*10 + NG*128 + NG*64) * 4)

// ---------------- device scratch (zero at load; kept zeroed by k_mlp each call) ----------------
__device__ int   g_deg[NN];
__device__ int   g_cursor[NB];
__device__ int   g_ncursor[NB];
__device__ int   g_perm2[NB * EE];
__device__ int   g_nperm[NB * NN];
__device__ float g_y[NN * INF_];
__device__ float g_xA[NN * INF_];
__device__ float g_xB[NN * INF_];
__device__ float g_pooled[NG * 10];

// ---------------- helpers ----------------
__device__ __forceinline__ unsigned f2tf32(float f) {
    unsigned u; asm("cvt.rna.tf32.f32 %0, %1;" : "=r"(u) : "f"(f)); return u;
}
__device__ __forceinline__ void mma_tf32(float* c, unsigned a0, unsigned a1, unsigned a2, unsigned a3,
                                         unsigned b0, unsigned b1) {
    asm volatile("mma.sync.aligned.m16n8k8.row.col.f32.tf32.tf32.f32 "
                 "{%0,%1,%2,%3}, {%4,%5,%6,%7}, {%8,%9}, {%0,%1,%2,%3};"
                 : "+f"(c[0]), "+f"(c[1]), "+f"(c[2]), "+f"(c[3])
                 : "r"(a0), "r"(a1), "r"(a2), "r"(a3), "r"(b0), "r"(b1));
}
// sigmoid(x) = 0.5*tanh(x/2) + 0.5  (single MUFU via tanh.approx)
__device__ __forceinline__ float sigf(float x) {
    float t;
    float h = 0.5f * x;
    asm("tanh.approx.f32 %0, %1;" : "=f"(t) : "f"(h));
    return fmaf(0.5f, t, 0.5f);
}
__device__ __forceinline__ void red4(float* p, float4 v) {
    asm volatile("red.global.add.v4.f32 [%0], {%1, %2, %3, %4};"
                 :: "l"(p), "f"(v.x), "f"(v.y), "f"(v.z), "f"(v.w) : "memory");
}

// ---------------- preprocessing ----------------
__global__ void k_deg(const int* __restrict__ ei) {
    int e = blockIdx.x * blockDim.x + threadIdx.x;
    if (e < EE) atomicAdd(&g_deg[ei[e]], 1);
}

// fused node+edge two-level scatter (smem histograms, ranged global atomics)
__global__ void k_scatterBoth(const int* __restrict__ ei) {
    __shared__ int ecnt[NB], ern[NB];
    __shared__ int ncnt[NB], nrn[NB];
    int tid = threadIdx.x;
    if (tid < NB) { ecnt[tid] = 0; ncnt[tid] = 0; }
    __syncthreads();
    int idx = blockIdx.x * blockDim.x + tid;
    int eb = -1, epos = 0, nb = -1, npos = 0;
    if (idx < EE) {
        eb = min(g_deg[ei[idx]] + 1, NB) - 1;
        epos = atomicAdd(&ecnt[eb], 1);
    }
    if (idx < NN) {
        nb = min(g_deg[idx] + 1, NB) - 1;
        npos = atomicAdd(&ncnt[nb], 1);
    }
    __syncthreads();
    if (tid < NB) {
        ern[tid] = ecnt[tid] ? atomicAdd(&g_cursor[tid], ecnt[tid]) : 0;
        nrn[tid] = ncnt[tid] ? atomicAdd(&g_ncursor[tid], ncnt[tid]) : 0;
    }
    __syncthreads();
    if (idx < EE) g_perm2[eb * EE + ern[eb] + epos] = idx;
    if (idx < NN) g_nperm[nb * NN + nrn[nb] + npos] = idx;
}

// ---------------- node GEMM: y = x @ W_top[bucket(n)]; xout init = sigf(y) ----------------
__global__ __launch_bounds__(TPB, 4) void k_node(
    const float* __restrict__ xin, const float* __restrict__ Wt,
    float* __restrict__ xout)
{
    cudaTriggerProgrammaticLaunchCompletion();

    extern __shared__ unsigned sm[];
    unsigned* Wts = sm;                   // [64][32 pairs] stride NIS
    unsigned* A   = sm + 64 * NIS;        // [TMN][32 pairs] stride NIS
    int* nidS = (int*)(A + TMN * NIS);

    const int tid = threadIdx.x;
    __shared__ int scnt[NB];
    __shared__ int s_bucket, s_loc, s_cnt;
    if (tid < NB) scnt[tid] = g_ncursor[tid];
    __syncthreads();
    if (tid == 0) {
        int acc = 0, b = -1, loc = 0, cnt = 0;
        #pragma unroll
        for (int i = 0; i < NB; i++) {
            int nt = (scnt[i] + TMN - 1) >> 6;
            if (b < 0 && (int)blockIdx.x < acc + nt) { b = i; loc = blockIdx.x - acc; cnt = scnt[i]; }
            acc += nt;
        }
        s_bucket = b; s_loc = loc; s_cnt = cnt;
    }
    __syncthreads();
    const int bucket = s_bucket;
    if (bucket < 0) return;
    const int cnt  = s_cnt;
    const int base = s_loc * TMN;

    const float* Wg = Wt + bucket * KD * 64;
    #pragma unroll
    for (int idx = tid; idx < 64 * 32; idx += TPB) {
        int c = idx & 63, p = idx >> 6;
        int kc = p >> 2, j = p & 3;
        int r0 = kc * 8 + j;
        uint2 u = make_uint2(f2tf32(Wg[r0 * 64 + c]), f2tf32(Wg[(r0 + 4) * 64 + c]));
        *(uint2*)(Wts + c * NIS + p * 2) = u;
    }
    if (tid < TMN)
        nidS[tid] = (base + tid < cnt) ? g_nperm[bucket * NN + base + tid] : -1;
    __syncthreads();

    // wait for predecessor (xin producer) before gathering x
    cudaGridDependencySynchronize();

    const float4* xin4 = (const float4*)xin;
    #pragma unroll
    for (int idx = tid; idx < TMN * 8; idx += TPB) {
        int r = idx >> 3, kc = idx & 7;
        int nid = nidS[r];
        float4 v0 = make_float4(0.f,0.f,0.f,0.f), v1 = v0;
        if (nid >= 0) { v0 = xin4[nid * 16 + kc * 2]; v1 = xin4[nid * 16 + kc * 2 + 1]; }
        unsigned* p = A + r * NIS + kc * 8;
        *(uint2*)(p + 0) = make_uint2(f2tf32(v0.x), f2tf32(v1.x));
        *(uint2*)(p + 2) = make_uint2(f2tf32(v0.y), f2tf32(v1.y));
        *(uint2*)(p + 4) = make_uint2(f2tf32(v0.z), f2tf32(v1.z));
        *(uint2*)(p + 6) = make_uint2(f2tf32(v0.w), f2tf32(v1.w));
    }
    __syncthreads();

    const int warp = tid >> 5, lane = tid & 31;
    const int g = lane >> 2, tg = lane & 3;
    const int rowbase = (warp >> 1) * 16;
    const int ch = warp & 1;

    float acc[4][4];
    #pragma unroll
    for (int n = 0; n < 4; n++)
        #pragma unroll
        for (int j = 0; j < 4; j++) acc[n][j] = 0.f;

    const unsigned* A0 = A + (rowbase + g) * NIS + tg * 2;
    const unsigned* A1 = A0 + 8 * NIS;
    const unsigned* Bb = Wts + (ch * 32 + g) * NIS + tg * 2;

    #pragma unroll
    for (int kc = 0; kc < 8; kc++) {
        const int ko = kc * 8;
        uint2 pa0 = *(const uint2*)(A0 + ko);
        uint2 pa1 = *(const uint2*)(A1 + ko);
        #pragma unroll
        for (int nc = 0; nc < 4; nc++) {
            uint2 pb = *(const uint2*)(Bb + nc * 8 * NIS + ko);
            mma_tf32(acc[nc], pa0.x, pa1.x, pa0.y, pa1.y, pb.x, pb.y);
        }
    }

    const int r0 = rowbase + g, r1 = r0 + 8;
    const int n0 = nidS[r0], n1 = nidS[r1];
    #pragma unroll
    for (int nc = 0; nc < 4; nc++) {
        int coff = ch * 32 + nc * 8 + tg * 2;
        if (n0 >= 0) {
            *(float2*)(g_y + n0 * 64 + coff) = make_float2(acc[nc][0], acc[nc][1]);
            *(float2*)(xout + n0 * 64 + coff) = make_float2(sigf(acc[nc][0]), sigf(acc[nc][1]));
        }
        if (n1 >= 0) {
            *(float2*)(g_y + n1 * 64 + coff) = make_float2(acc[nc][2], acc[nc][3]);
            *(float2*)(xout + n1 * 64 + coff) = make_float2(sigf(acc[nc][2]), sigf(acc[nc][3]));
        }
    }
}

// ---------------- edge GEMM + fused aggregation (512 threads, paired-warp mapping) ----------------
// PDL: everything through the MMA depends only on preprocessing/const inputs;
// sync just before the epilogue. 16 outputs/thread -> reg target 42, 3 blocks/SM.
__global__ __launch_bounds__(TPBE, 3) void k_edge(
    const float* __restrict__ ea, const int* __restrict__ ei,
    const float* __restrict__ Wt, float* __restrict__ xout)
{
    cudaTriggerProgrammaticLaunchCompletion();

    extern __shared__ unsigned sm[];
    unsigned* Wts = sm;                   // [64][8 pairs] stride EIS
    unsigned* A   = sm + 64 * EIS;        // [TME][8 pairs] stride EIS
    int* eS   = (int*)(A + TME * EIS);
    int* srcS = eS + TME;
    int* dstS = srcS + TME;

    const int tid = threadIdx.x;
    __shared__ int scnt[NB];
    __shared__ int s_bucket, s_loc, s_cnt;
    if (tid < NB) scnt[tid] = g_cursor[tid];
    __syncthreads();
    if (tid == 0) {
        int acc = 0, b = -1, loc = 0, cnt = 0;
        #pragma unroll
        for (int i = 0; i < NB; i++) {
            int nt = (scnt[i] + TME - 1) >> 7;
            if (b < 0 && (int)blockIdx.x < acc + nt) { b = i; loc = blockIdx.x - acc; cnt = scnt[i]; }
            acc += nt;
        }
        s_bucket = b; s_loc = loc; s_cnt = cnt;
    }
    __syncthreads();
    const int bucket = s_bucket;
    if (bucket < 0) return;
    const int cnt  = s_cnt;
    const int base = s_loc * TME;

    // stage W_bot rows 64..79
    const float* Wg = Wt + bucket * KD * 64;
    #pragma unroll
    for (int idx = tid; idx < 64 * 8; idx += TPBE) {
        int c = idx & 63, p = idx >> 6;
        int kc = p >> 2, j = p & 3;
        int r0 = 64 + kc * 8 + j;
        uint2 u = make_uint2(f2tf32(Wg[r0 * 64 + c]), f2tf32(Wg[(r0 + 4) * 64 + c]));
        *(uint2*)(Wts + c * EIS + p * 2) = u;
    }
    if (tid < TME) {
        int r = tid;
        int e = -1, s = 0, d = -1;
        if (base + r < cnt) {
            e = g_perm2[bucket * EE + base + r];
            s = ei[e];
            d = ei[EE + e];
        }
        eS[r] = e; srcS[r] = s; dstS[r] = d;
    }
    __syncthreads();

    const float4* ea4 = (const float4*)ea;
    for (int idx = tid; idx < TME * 2; idx += TPBE) {
        int r = idx >> 1, kc = idx & 1;
        int e = eS[r];
        float4 v0 = make_float4(0.f,0.f,0.f,0.f), v1 = v0;
        if (e >= 0) { v0 = ea4[e * 4 + kc * 2]; v1 = ea4[e * 4 + kc * 2 + 1]; }
        unsigned* p = A + r * EIS + kc * 8;
        *(uint2*)(p + 0) = make_uint2(f2tf32(v0.x), f2tf32(v1.x));
        *(uint2*)(p + 2) = make_uint2(f2tf32(v0.y), f2tf32(v1.y));
        *(uint2*)(p + 4) = make_uint2(f2tf32(v0.z), f2tf32(v1.z));
        *(uint2*)(p + 6) = make_uint2(f2tf32(v0.w), f2tf32(v1.w));
    }
    __syncthreads();

    // 16 warps: row-tile = warp>>1 (16 rows), col-half = warp&1 (32 cols)
    const int warp = tid >> 5, lane = tid & 31;
    const int g = lane >> 2, tg = lane & 3;
    const int rowbase = (warp >> 1) * 16;
    const int ch = warp & 1;

    float acc[4][4];
    #pragma unroll
    for (int n = 0; n < 4; n++)
        #pragma unroll
        for (int j = 0; j < 4; j++) acc[n][j] = 0.f;

    const unsigned* A0 = A + (rowbase + g) * EIS + tg * 2;
    const unsigned* A1 = A0 + 8 * EIS;
    const unsigned* Bb = Wts + (ch * 32 + g) * EIS + tg * 2;

    #pragma unroll
    for (int kc = 0; kc < 2; kc++) {
        const int ko = kc * 8;
        uint2 pa0 = *(const uint2*)(A0 + ko);
        uint2 pa1 = *(const uint2*)(A1 + ko);
        #pragma unroll
        for (int nc = 0; nc < 4; nc++) {
            uint2 pb = *(const uint2*)(Bb + nc * 8 * EIS + ko);
            mma_tf32(acc[nc], pa0.x, pa1.x, pa0.y, pa1.y, pb.x, pb.y);
        }
    }

    // wait for predecessor (k_node: g_y + xout init) before the epilogue
    cudaGridDependencySynchronize();

    // epilogue: lane-pair shuffle -> 4 contiguous cols per lane; v4 gather + v4 reduction
    const int r0 = rowbase + g, r1 = r0 + 8;
    const bool odd = tg & 1;
    const int myE = odd ? eS[r1]   : eS[r0];
    const int myS = odd ? srcS[r1] : srcS[r0];
    const int myD = odd ? dstS[r1] : dstS[r0];
    const int colbase = (tg & ~1) * 2;
    #pragma unroll
    for (int nc = 0; nc < 4; nc++) {
        float sx = odd ? acc[nc][0] : acc[nc][2];
        float sy = odd ? acc[nc][1] : acc[nc][3];
        float rx = __shfl_xor_sync(0xffffffffu, sx, 1);
        float ry = __shfl_xor_sync(0xffffffffu, sy, 1);
        float4 z4;
        if (odd) { z4.x = rx;          z4.y = ry;          z4.z = acc[nc][2]; z4.w = acc[nc][3]; }
        else     { z4.x = acc[nc][0];  z4.y = acc[nc][1];  z4.z = rx;         z4.w = ry;         }
        if (myE >= 0) {
            int col = ch * 32 + nc * 8 + colbase;
            float4 yv = *(const float4*)(g_y + (size_t)myS * 64 + col);
            float4 v = make_float4(sigf(z4.x + yv.x), sigf(z4.y + yv.y),
                                   sigf(z4.z + yv.z), sigf(z4.w + yv.w));
            red4(xout + (size_t)myD * 64 + col, v);
        }
    }
}

// ---------------- readout (PDL: W staging pre-sync) ----------------
__global__ __launch_bounds__(TPB) void k_readout(
    const float* __restrict__ x, const float* __restrict__ Wread,
    const int* __restrict__ batch)
{
    cudaTriggerProgrammaticLaunchCompletion();

    __shared__ float Ws[TSTEPS * INF_ * 10];
    for (int i = threadIdx.x; i < TSTEPS * INF_ * 10; i += TPB) Ws[i] = Wread[i];
    __syncthreads();

    cudaGridDependencySynchronize();

    int n = blockIdx.x * blockDim.x + threadIdx.x;
    if (n >= NN) return;

    float xr[INF_];
    const float4* xp = (const float4*)(x + n * INF_);
    #pragma unroll
    for (int q = 0; q < INF_ / 4; q++) {
        float4 f = xp[q];
        xr[q*4+0] = f.x; xr[q*4+1] = f.y; xr[q*4+2] = f.z; xr[q*4+3] = f.w;
    }

    float accq[10];
    #pragma unroll
    for (int j = 0; j < 10; j++) accq[j] = 0.f;

    for (int t = 0; t < TSTEPS; t++) {
        float l[10];
        #pragma unroll
        for (int j = 0; j < 10; j++) l[j] = 0.f;
        const float* W = Ws + t * INF_ * 10;
        #pragma unroll 4
        for (int k = 0; k < INF_; k++) {
            float xv = xr[k];
            #pragma unroll
            for (int j = 0; j < 10; j++) l[j] += xv * W[k * 10 + j];
        }
        float m = l[0];
        #pragma unroll
        for (int j = 1; j < 10; j++) m = fmaxf(m, l[j]);
        float ssum = 0.f;
        #pragma unroll
        for (int j = 0; j < 10; j++) { l[j] = __expf(l[j] - m); ssum += l[j]; }
        float inv = 1.f / ssum;
        #pragma unroll
        for (int j = 0; j < 10; j++) accq[j] += l[j] * inv;
    }

    int g = batch[n];
    #pragma unroll
    for (int j = 0; j < 10; j++) atomicAdd(&g_pooled[g * 10 + j], accq[j]);
}

// ---------------- final MLP + graph-state reset ----------------
__global__ __launch_bounds__(TPB) void k_mlp(
    const float* __restrict__ fc1w, const float* __restrict__ fc1b,
    const float* __restrict__ fc2w, const float* __restrict__ fc2b,
    const float* __restrict__ fc3w, const float* __restrict__ fc3b,
    float* __restrict__ out)
{
    extern __shared__ float smf[];
    float* P  = smf;
    float* H1 = P + NG * 10;
    float* H2 = H1 + NG * 128;
    int tid = threadIdx.x;

    for (int i = tid; i < NG * 10; i += TPB) P[i] = g_pooled[i];
    __syncthreads();

    // reset device state so the graph is replay-invariant
    for (int i = tid; i < NN; i += TPB) g_deg[i] = 0;
    if (tid < NB) { g_cursor[tid] = 0; g_ncursor[tid] = 0; }
    for (int i = tid; i < NG * 10; i += TPB) g_pooled[i] = 0.f;

    for (int idx = tid; idx < NG * 128; idx += TPB) {
        int g = idx >> 7, j = idx & 127;
        float a = fc1b[j];
        #pragma unroll
        for (int k = 0; k < 10; k++) a += P[g * 10 + k] * fc1w[k * 128 + j];
        H1[idx] = a > 0.f ? a : 0.01f * a;
    }
    __syncthreads();

    for (int idx = tid; idx < NG * 64; idx += TPB) {
        int g = idx >> 6, j = idx & 63;
        float a = fc2b[j];
        #pragma unroll 8
        for (int k = 0; k < 128; k++) a += H1[g * 128 + k] * fc2w[k * 64 + j];
        H2[idx] = a > 0.f ? a : 0.01f * a;
    }
    __syncthreads();

    for (int g = tid; g < NG; g += TPB) {
        float a = fc3b[0];
        #pragma unroll 8
        for (int k = 0; k < 64; k++) a += H2[g * 64 + k] * fc3w[k];
        out[g] = a > 0.f ? a : 0.01f * a;
    }
}

// ---------------- launch ----------------
extern "C" void kernel_launch(void* const* d_in, const int* in_sizes, int n_in,
                              void* d_out, int out_size)
{
    const float* x     = (const float*)d_in[0];
    const float* ea    = (const float*)d_in[1];
    const float* Wmsg  = (const float*)d_in[2];
    const float* Wread = (const float*)d_in[3];
    const float* fc1w  = (const float*)d_in[4];
    const float* fc1b  = (const float*)d_in[5];
    const float* fc2w  = (const float*)d_in[6];
    const float* fc2b  = (const float*)d_in[7];
    const float* fc3w  = (const float*)d_in[8];
    const float* fc3b  = (const float*)d_in[9];
    const int*   ei    = (const int*)d_in[10];
    const int*   batch = (const int*)d_in[11];
    float* out = (float*)d_out;

    cudaFuncSetAttribute(k_node, cudaFuncAttributeMaxDynamicSharedMemorySize, NODE_SMEM);
    cudaFuncSetAttribute(k_edge, cudaFuncAttributeMaxDynamicSharedMemorySize, EDGE_SMEM);
    cudaFuncSetAttribute(k_mlp,  cudaFuncAttributeMaxDynamicSharedMemorySize, MLP_SMEM);

    void *pA = nullptr, *pB = nullptr;
    cudaGetSymbolAddress(&pA, g_xA);
    cudaGetSymbolAddress(&pB, g_xB);

    k_deg<<<(EE + TPB - 1) / TPB, TPB>>>(ei);
    k_scatterBoth<<<(EE + TPB - 1) / TPB, TPB>>>(ei);

    // PDL launch config
    cudaLaunchAttribute pdlAttr[1];
    pdlAttr[0].id = cudaLaunchAttributeProgrammaticStreamSerialization;
    pdlAttr[0].val.programmaticStreamSerializationAllowed = 1;

    cudaLaunchConfig_t cfgNode = {};
    cfgNode.gridDim = dim3(NTILEN);
    cfgNode.blockDim = dim3(TPB);
    cfgNode.dynamicSmemBytes = NODE_SMEM;
    cfgNode.stream = 0;
    cfgNode.attrs = pdlAttr;
    cfgNode.numAttrs = 1;

    cudaLaunchConfig_t cfgEdge = {};
    cfgEdge.gridDim = dim3(NTILEE);
    cfgEdge.blockDim = dim3(TPBE);
    cfgEdge.dynamicSmemBytes = EDGE_SMEM;
    cfgEdge.stream = 0;
    cfgEdge.attrs = pdlAttr;
    cfgEdge.numAttrs = 1;

    cudaLaunchConfig_t cfgRead = {};
    cfgRead.gridDim = dim3((NN + TPB - 1) / TPB);
    cfgRead.blockDim = dim3(TPB);
    cfgRead.dynamicSmemBytes = 0;
    cfgRead.stream = 0;
    cfgRead.attrs = pdlAttr;
    cfgRead.numAttrs = 1;

    const float* xin = x;
    for (int t = 0; t < TSTEPS; t++) {
        const float* Wt = Wmsg + (size_t)t * NB * KD * INF_;
        float* xo = (t % 2 == 0) ? (float*)pB : (float*)pA;
        if (t == 0) {
            // k_node reads g_ncursor (written by immediate predecessor) pre-sync -> serialize.
            k_node<<<NTILEN, TPB, NODE_SMEM>>>(xin, Wt, xo);
        } else {
            cudaLaunchKernelEx(&cfgNode, k_node, xin, Wt, xo);
        }
        cudaLaunchKernelEx(&cfgEdge, k_edge, ea, ei, Wt, xo);
        xin = xo;
    }

    cudaLaunchKernelEx(&cfgRead, k_readout, xin, Wread, batch);
    k_mlp<<<1, TPB, MLP_SMEM>>>(fc1w, fc1b, fc2w, fc2b, fc3w, fc3b, out);
}